// round 1
// baseline (speedup 1.0000x reference)
#include <cuda_runtime.h>
#include <math.h>

#define BB 128
#define SS 400
#define ENCD 1024
#define DECD 300
#define EMBD 128
#define VOCAB 50000
#define MAXOOV 50
#define PVC (VOCAB + MAXOOV)   /* 50050 */
#define RNNK (EMBD + ENCD)     /* 1152 */
#define HWK (DECD + ENCD)      /* 1324 */
#define G3 (3 * DECD)          /* 900 */

// ---------------- scratch (static device globals; no allocation) ----------
__device__ __align__(256) float g_v[BB * ENCD];
__device__ __align__(256) float g_rnn[BB * RNNK];
__device__ __align__(256) float g_gx[BB * G3];
__device__ __align__(256) float g_gh[BB * G3];
__device__ __align__(256) float g_hw[BB * HWK];
__device__ __align__(256) float g_a2[BB * SS];
__device__ __align__(256) float g_pgen[BB];
__device__ __align__(256) float g_logits[(size_t)BB * VOCAB];

// ---------------- generic SGEMM: C[M,N] = A[M,K] * B[N,K]^T (+bias) -------
// 128x64 block tile, 16 K-tile, 8x4 per-thread microtile, 256 threads.
__global__ __launch_bounds__(256, 1)
void sgemm_abt(const float* __restrict__ A, int lda,
               const float* __restrict__ B, int ldb,
               float* __restrict__ C, int ldc,
               const float* __restrict__ bias,
               int M, int N, int K)
{
    constexpr int BM = 128, BN = 64, BK = 16, TM = 8, TN = 4;
    __shared__ __align__(16) float As[BK][BM + 4];
    __shared__ __align__(16) float Bs[BK][BN + 4];
    const int tid = threadIdx.x;
    const int bm = blockIdx.y * BM;
    const int bn = blockIdx.x * BN;
    const int tm = (tid >> 4) * TM;   // 0..120
    const int tn = (tid & 15) * TN;   // 0..60
    float acc[TM][TN] = {};

    const int brow = tid >> 2;        // 0..63 (B loader row)
    const int blk  = (tid & 3) << 2;  // 0,4,8,12

    for (int k0 = 0; k0 < K; k0 += BK) {
        // load A tile (128x16): 512 float4 chunks, 2 per thread
#pragma unroll
        for (int c = 0; c < 2; c++) {
            int idx = tid + c * 256;
            int arow = idx >> 2;
            int ak = (idx & 3) << 2;
            int gm = bm + arow, gk = k0 + ak;
            float4 t = make_float4(0.f, 0.f, 0.f, 0.f);
            if (gm < M && gk < K) {
                const float* p = A + (size_t)gm * lda + gk;
                if (gk + 3 < K) t = *(const float4*)p;
                else { t.x = p[0]; if (gk + 1 < K) t.y = p[1]; if (gk + 2 < K) t.z = p[2]; }
            }
            As[ak + 0][arow] = t.x; As[ak + 1][arow] = t.y;
            As[ak + 2][arow] = t.z; As[ak + 3][arow] = t.w;
        }
        // load B tile (64x16): 256 float4 chunks, 1 per thread
        {
            int gn = bn + brow, gk = k0 + blk;
            float4 t = make_float4(0.f, 0.f, 0.f, 0.f);
            if (gn < N && gk < K) {
                const float* p = B + (size_t)gn * ldb + gk;
                if (gk + 3 < K) t = *(const float4*)p;
                else { t.x = p[0]; if (gk + 1 < K) t.y = p[1]; if (gk + 2 < K) t.z = p[2]; }
            }
            Bs[blk + 0][brow] = t.x; Bs[blk + 1][brow] = t.y;
            Bs[blk + 2][brow] = t.z; Bs[blk + 3][brow] = t.w;
        }
        __syncthreads();
#pragma unroll
        for (int kk = 0; kk < BK; kk++) {
            float4 a0 = *(const float4*)&As[kk][tm];
            float4 a1 = *(const float4*)&As[kk][tm + 4];
            float4 b0 = *(const float4*)&Bs[kk][tn];
            float ar[TM] = {a0.x, a0.y, a0.z, a0.w, a1.x, a1.y, a1.z, a1.w};
            float br[TN] = {b0.x, b0.y, b0.z, b0.w};
#pragma unroll
            for (int i = 0; i < TM; i++)
#pragma unroll
                for (int j = 0; j < TN; j++)
                    acc[i][j] = fmaf(ar[i], br[j], acc[i][j]);
        }
        __syncthreads();
    }
#pragma unroll
    for (int i = 0; i < TM; i++) {
        int row = bm + tm + i;
        if (row >= M) continue;
#pragma unroll
        for (int j = 0; j < TN; j++) {
            int col = bn + tn + j;
            if (col < N) {
                float r = acc[i][j];
                if (bias) r += bias[col];
                C[(size_t)row * ldc + col] = r;
            }
        }
    }
}

// ---------------- fused attention: scores -> softmax -> weighted ----------
// block per batch row b. Pass 1: warp-per-s dot(enc[b,s,:], v[b,:]).
// Softmax over S in smem. Pass 2: thread-per-4e weighted sum over s.
__global__ __launch_bounds__(256, 1)
void attn_kernel(const float* __restrict__ enc,
                 const float* __restrict__ v,
                 const unsigned char* __restrict__ pad,
                 float* __restrict__ wout, int wstride,
                 float* __restrict__ a_out)
{
    const int b = blockIdx.x;
    const int tid = threadIdx.x;
    const int lane = tid & 31, warp = tid >> 5;
    __shared__ __align__(16) float vsh[ENCD];
    __shared__ float sc[SS];
    __shared__ float red[8];
    const float* encb = enc + (size_t)b * SS * ENCD;

    ((float4*)vsh)[tid] = ((const float4*)(v + (size_t)b * ENCD))[tid];
    __syncthreads();

    const float4* vv = (const float4*)vsh;
    for (int s = warp; s < SS; s += 8) {
        const float4* row = (const float4*)(encb + (size_t)s * ENCD);
        float acc = 0.f;
#pragma unroll
        for (int i = 0; i < ENCD / 128; i++) {
            float4 e4 = row[lane + 32 * i];
            float4 v4 = vv[lane + 32 * i];
            acc = fmaf(e4.x, v4.x, acc);
            acc = fmaf(e4.y, v4.y, acc);
            acc = fmaf(e4.z, v4.z, acc);
            acc = fmaf(e4.w, v4.w, acc);
        }
#pragma unroll
        for (int o = 16; o; o >>= 1) acc += __shfl_xor_sync(0xffffffffu, acc, o);
        if (lane == 0) sc[s] = pad[(size_t)b * SS + s] ? -INFINITY : acc;
    }
    __syncthreads();

    // block max
    float m = -INFINITY;
    for (int i = tid; i < SS; i += 256) m = fmaxf(m, sc[i]);
#pragma unroll
    for (int o = 16; o; o >>= 1) m = fmaxf(m, __shfl_xor_sync(0xffffffffu, m, o));
    if (lane == 0) red[warp] = m;
    __syncthreads();
    if (tid == 0) {
        float mm = red[0];
        for (int w = 1; w < 8; w++) mm = fmaxf(mm, red[w]);
        red[0] = mm;
    }
    __syncthreads();
    m = red[0];
    __syncthreads();

    // exp + block sum
    float lsum = 0.f;
    for (int i = tid; i < SS; i += 256) {
        float e = __expf(sc[i] - m);
        sc[i] = e;
        lsum += e;
    }
#pragma unroll
    for (int o = 16; o; o >>= 1) lsum += __shfl_xor_sync(0xffffffffu, lsum, o);
    if (lane == 0) red[warp] = lsum;
    __syncthreads();
    if (tid == 0) {
        float t = 0.f;
        for (int w = 0; w < 8; w++) t += red[w];
        red[0] = t;
    }
    __syncthreads();
    float inv = 1.f / red[0];
    for (int i = tid; i < SS; i += 256) {
        float a = sc[i] * inv;
        sc[i] = a;
        if (a_out) a_out[(size_t)b * SS + i] = a;
    }
    __syncthreads();

    // weighted[b, e0..e0+3] = sum_s a[s] * enc[b,s,e]
    const int e0 = tid * 4;
    float wx = 0.f, wy = 0.f, wz = 0.f, ww = 0.f;
#pragma unroll 4
    for (int s = 0; s < SS; s++) {
        float a = sc[s];
        float4 e4 = *(const float4*)(encb + (size_t)s * ENCD + e0);
        wx = fmaf(a, e4.x, wx);
        wy = fmaf(a, e4.y, wy);
        wz = fmaf(a, e4.z, wz);
        ww = fmaf(a, e4.w, ww);
    }
    *(float4*)(wout + (size_t)b * wstride + e0) = make_float4(wx, wy, wz, ww);
}

// ---------------- small elementwise / glue kernels -------------------------
__global__ void embed_copy(const float* __restrict__ emb)
{
    int i = blockIdx.x * blockDim.x + threadIdx.x;
    if (i < BB * EMBD) {
        int b = i / EMBD, j = i - b * EMBD;
        g_rnn[(size_t)b * RNNK + j] = emb[i];
    }
}

__global__ void gru_combine(const float* __restrict__ h1,
                            float* __restrict__ out_h, int write_out)
{
    int i = blockIdx.x * blockDim.x + threadIdx.x;
    if (i >= BB * DECD) return;
    int b = i / DECD, j = i - b * DECD;
    const float* gx = g_gx + (size_t)b * G3;
    const float* gh = g_gh + (size_t)b * G3;
    float r = 1.f / (1.f + __expf(-(gx[j] + gh[j])));
    float z = 1.f / (1.f + __expf(-(gx[j + DECD] + gh[j + DECD])));
    float n = tanhf(gx[j + 2 * DECD] + r * gh[j + 2 * DECD]);
    float h = (1.f - z) * n + z * h1[i];
    g_hw[(size_t)b * HWK + j] = h;
    if (write_out) out_h[i] = h;
}

__global__ __launch_bounds__(128)
void pgen_kernel(const float* __restrict__ Wp, const float* __restrict__ bp)
{
    int b = blockIdx.x, tid = threadIdx.x;
    int lane = tid & 31, warp = tid >> 5;
    __shared__ float red[4];
    const float* hwb = g_hw + (size_t)b * HWK;
    float acc = 0.f;
    for (int i = tid; i < HWK; i += 128) acc = fmaf(hwb[i], Wp[i], acc);
#pragma unroll
    for (int o = 16; o; o >>= 1) acc += __shfl_xor_sync(0xffffffffu, acc, o);
    if (lane == 0) red[warp] = acc;
    __syncthreads();
    if (tid == 0) {
        float t = red[0] + red[1] + red[2] + red[3] + bp[0];
        g_pgen[b] = 1.f / (1.f + __expf(-t));
    }
}

__global__ __launch_bounds__(256)
void pvocab_kernel(float* __restrict__ pout)
{
    int b = blockIdx.x, tid = threadIdx.x;
    int lane = tid & 31, warp = tid >> 5;
    __shared__ float red[8];
    __shared__ float bc[2];
    const float* lg = g_logits + (size_t)b * VOCAB;

    float m = -INFINITY;
    for (int i = tid; i < VOCAB; i += 256) m = fmaxf(m, lg[i]);
#pragma unroll
    for (int o = 16; o; o >>= 1) m = fmaxf(m, __shfl_xor_sync(0xffffffffu, m, o));
    if (lane == 0) red[warp] = m;
    __syncthreads();
    if (tid == 0) {
        float mm = red[0];
        for (int w = 1; w < 8; w++) mm = fmaxf(mm, red[w]);
        bc[0] = mm;
    }
    __syncthreads();
    m = bc[0];

    float s = 0.f;
    for (int i = tid; i < VOCAB; i += 256) s += __expf(lg[i] - m);
#pragma unroll
    for (int o = 16; o; o >>= 1) s += __shfl_xor_sync(0xffffffffu, s, o);
    if (lane == 0) red[warp] = s;
    __syncthreads();
    if (tid == 0) {
        float t = 0.f;
        for (int w = 0; w < 8; w++) t += red[w];
        bc[1] = t;
    }
    __syncthreads();

    float scale = g_pgen[b] / bc[1];
    float* row = pout + (size_t)b * PVC;
    for (int i = tid; i < VOCAB; i += 256) row[i] = __expf(lg[i] - m) * scale;
    for (int i = VOCAB + tid; i < PVC; i += 256) row[i] = 0.f;
}

__global__ void scatter_kernel(const int* __restrict__ src, float* __restrict__ pout)
{
    int i = blockIdx.x * blockDim.x + threadIdx.x;
    if (i >= BB * SS) return;
    int b = i / SS;
    float val = (1.f - g_pgen[b]) * g_a2[i];
    atomicAdd(pout + (size_t)b * PVC + src[i], val);
}

// ---------------- launch ---------------------------------------------------
extern "C" void kernel_launch(void* const* d_in, const int* in_sizes, int n_in,
                              void* d_out, int out_size)
{
    // input index map; max_n_oov (scalar) may be dropped by the harness
    int off = (n_in >= 16) ? 0 : -1;
    const float* embedded = (const float*)d_in[0];
    const float* enc      = (const float*)d_in[1];
    const float* h1       = (const float*)d_in[2];
    const unsigned char* pad = (const unsigned char*)d_in[3];
    const int*   src      = (const int*)d_in[5 + off];
    const float* W_attn1  = (const float*)d_in[6 + off];
    const float* W_attn2  = (const float*)d_in[7 + off];
    const float* W_ih     = (const float*)d_in[8 + off];
    const float* W_hh     = (const float*)d_in[9 + off];
    const float* b_ih     = (const float*)d_in[10 + off];
    const float* b_hh     = (const float*)d_in[11 + off];
    const float* W_out    = (const float*)d_in[12 + off];
    const float* b_out    = (const float*)d_in[13 + off];
    const float* W_p      = (const float*)d_in[14 + off];
    const float* b_p      = (const float*)d_in[15 + off];
    float* pout = (float*)d_out;

    float *v, *rnn, *gx, *gh, *hw, *logits, *a2;
    cudaGetSymbolAddress((void**)&v, g_v);
    cudaGetSymbolAddress((void**)&rnn, g_rnn);
    cudaGetSymbolAddress((void**)&gx, g_gx);
    cudaGetSymbolAddress((void**)&gh, g_gh);
    cudaGetSymbolAddress((void**)&hw, g_hw);
    cudaGetSymbolAddress((void**)&logits, g_logits);
    cudaGetSymbolAddress((void**)&a2, g_a2);

    // 1. rnn[:, 0:EMB] = embedded
    embed_copy<<<(BB * EMBD + 255) / 256, 256>>>(embedded);
    // 2. v1 = h1 @ W_attn1^T            [128,1024]
    sgemm_abt<<<dim3(ENCD / 64, 1), 256>>>(h1, DECD, W_attn1, DECD, v, ENCD,
                                           nullptr, BB, ENCD, DECD);
    // 3. attn1 -> weighted1 into rnn[:, EMB:]
    attn_kernel<<<BB, 256>>>(enc, v, pad, rnn + EMBD, RNNK, nullptr);
    // 4. gx = rnn @ W_ih^T + b_ih       [128,900]
    sgemm_abt<<<dim3((G3 + 63) / 64, 1), 256>>>(rnn, RNNK, W_ih, RNNK, gx, G3,
                                                b_ih, BB, G3, RNNK);
    // 5. gh = h1 @ W_hh^T + b_hh        [128,900]
    sgemm_abt<<<dim3((G3 + 63) / 64, 1), 256>>>(h1, DECD, W_hh, DECD, gh, G3,
                                                b_hh, BB, G3, DECD);
    // 6. GRU combine -> hw[:, 0:DEC] (= h_new), and output tail if present
    int wtail = (out_size >= BB * PVC + BB * DECD) ? 1 : 0;
    gru_combine<<<(BB * DECD + 255) / 256, 256>>>(h1, pout + (size_t)BB * PVC, wtail);
    // 7. v2 = h_new @ W_attn2^T   (A = hw with lda=HWK, K=DEC)
    sgemm_abt<<<dim3(ENCD / 64, 1), 256>>>(hw, HWK, W_attn2, DECD, v, ENCD,
                                           nullptr, BB, ENCD, DECD);
    // 8. attn2 -> weighted2 into hw[:, DEC:], save a2
    attn_kernel<<<BB, 256>>>(enc, v, pad, hw + DECD, HWK, a2);
    // 9. p_gen = sigmoid(hw @ W_p^T + b_p)
    pgen_kernel<<<BB, 128>>>(W_p, b_p);
    // 10. logits = hw @ W_out^T + b_out  [128, 50000]  (the big one)
    sgemm_abt<<<dim3((VOCAB + 63) / 64, 1), 256>>>(hw, HWK, W_out, HWK, logits,
                                                   VOCAB, b_out, BB, VOCAB, HWK);
    // 11. p_out[:, :VOCAB] = p_gen * softmax(logits); ext cols zeroed
    pvocab_kernel<<<BB, 256>>>(pout);
    // 12. scatter-add (1-p_gen)*a2 at source ids (atomic: duplicate ids exist)
    scatter_kernel<<<(BB * SS + 255) / 256, 256>>>(src, pout);
}

// round 2
// speedup vs baseline: 1.2251x; 1.2251x over previous
#include <cuda_runtime.h>
#include <math.h>

#define BB 128
#define SS 400
#define ENCD 1024
#define DECD 300
#define EMBD 128
#define VOCAB 50000
#define MAXOOV 50
#define PVC (VOCAB + MAXOOV)   /* 50050 */
#define RNNK (EMBD + ENCD)     /* 1152 */
#define HWK (DECD + ENCD)      /* 1324 */
#define G3 (3 * DECD)          /* 900 */

// ---------------- scratch (static device globals; no allocation) ----------
__device__ __align__(256) float g_v[BB * ENCD];
__device__ __align__(256) float g_rnn[BB * RNNK];
__device__ __align__(256) float g_gx[BB * G3];
__device__ __align__(256) float g_gh[BB * G3];
__device__ __align__(256) float g_hw[BB * HWK];
__device__ __align__(256) float g_a2[BB * SS];
__device__ __align__(256) float g_pgen[BB];
__device__ __align__(256) float g_logits[(size_t)BB * VOCAB];

// ====================================================================
// Small-GEMM path: C[M,N] = A[M,K] * B[N,K]^T (+bias).
// One warp computes 4 adjacent output columns for one row m.
// grid = (ceil(N/32), M), block = 256 (8 warps). K, N divisible by 4.
// Operands are L2-resident; this is latency-bound, so max parallelism.
// ====================================================================
__global__ __launch_bounds__(256)
void gemm_warp4(const float* __restrict__ A, int lda,
                const float* __restrict__ B, int ldb,
                float* __restrict__ C, int ldc,
                const float* __restrict__ bias, int N, int K)
{
    const int m = blockIdx.y;
    const int warp = threadIdx.x >> 5, lane = threadIdx.x & 31;
    const int n0 = blockIdx.x * 32 + warp * 4;
    if (n0 >= N) return;
    const float4* a = (const float4*)(A + (size_t)m * lda);
    const float4* b0 = (const float4*)(B + (size_t)(n0 + 0) * ldb);
    const float4* b1 = (const float4*)(B + (size_t)(n0 + 1) * ldb);
    const float4* b2 = (const float4*)(B + (size_t)(n0 + 2) * ldb);
    const float4* b3 = (const float4*)(B + (size_t)(n0 + 3) * ldb);
    const int K4 = K >> 2;
    float acc0 = 0.f, acc1 = 0.f, acc2 = 0.f, acc3 = 0.f;
    for (int i = lane; i < K4; i += 32) {
        float4 av = a[i];
        float4 v0 = b0[i], v1 = b1[i], v2 = b2[i], v3 = b3[i];
        acc0 = fmaf(av.x, v0.x, fmaf(av.y, v0.y, fmaf(av.z, v0.z, fmaf(av.w, v0.w, acc0))));
        acc1 = fmaf(av.x, v1.x, fmaf(av.y, v1.y, fmaf(av.z, v1.z, fmaf(av.w, v1.w, acc1))));
        acc2 = fmaf(av.x, v2.x, fmaf(av.y, v2.y, fmaf(av.z, v2.z, fmaf(av.w, v2.w, acc2))));
        acc3 = fmaf(av.x, v3.x, fmaf(av.y, v3.y, fmaf(av.z, v3.z, fmaf(av.w, v3.w, acc3))));
    }
#pragma unroll
    for (int o = 16; o; o >>= 1) {
        acc0 += __shfl_xor_sync(0xffffffffu, acc0, o);
        acc1 += __shfl_xor_sync(0xffffffffu, acc1, o);
        acc2 += __shfl_xor_sync(0xffffffffu, acc2, o);
        acc3 += __shfl_xor_sync(0xffffffffu, acc3, o);
    }
    if (lane == 0) {
        float* c = C + (size_t)m * ldc + n0;
        if (bias) {
            c[0] = acc0 + bias[n0 + 0];
            c[1] = acc1 + bias[n0 + 1];
            c[2] = acc2 + bias[n0 + 2];
            c[3] = acc3 + bias[n0 + 3];
        } else {
            c[0] = acc0; c[1] = acc1; c[2] = acc2; c[3] = acc3;
        }
    }
}

// ====================================================================
// Big SGEMM: C[M,N] = A[M,K] * B[N,K]^T (+bias).
// 128x128x16 tiles, 8x8 microtile, double-buffered smem, reg prefetch.
// Assumes M multiple-of usage covered by grid.y; K divisible by 4.
// ====================================================================
__global__ __launch_bounds__(256, 2)
void sgemm_big(const float* __restrict__ A, int lda,
               const float* __restrict__ B, int ldb,
               float* __restrict__ C, int ldc,
               const float* __restrict__ bias,
               int M, int N, int K)
{
    constexpr int BM = 128, BN = 128, BK = 16;
    __shared__ __align__(16) float As[2][BK][BM + 4];
    __shared__ __align__(16) float Bs[2][BK][BN + 4];
    const int tid = threadIdx.x;
    const int bm = blockIdx.y * BM;
    const int bn = blockIdx.x * BN;
    const int tm = (tid >> 4) * 8;     // 0..120
    const int tn = (tid & 15) * 8;     // 0..120
    const int r  = tid >> 2;           // 0..63
    const int k4 = (tid & 3) << 2;     // 0,4,8,12

    float acc[8][8] = {};
    float4 pa0, pa1, pb0, pb1;

    const int nk = (K + BK - 1) / BK;

    auto gload = [&](int kt) {
        const int gk = kt * BK + k4;
        const bool kv = (gk < K);                 // K % 4 == 0 -> whole float4 valid
        const float4 z = make_float4(0.f, 0.f, 0.f, 0.f);
        // A rows r, r+64
        {
            const int gm0 = bm + r, gm1 = bm + r + 64;
            pa0 = (kv && gm0 < M) ? *(const float4*)(A + (size_t)gm0 * lda + gk) : z;
            pa1 = (kv && gm1 < M) ? *(const float4*)(A + (size_t)gm1 * lda + gk) : z;
        }
        // B rows r, r+64
        {
            const int gn0 = bn + r, gn1 = bn + r + 64;
            pb0 = (kv && gn0 < N) ? *(const float4*)(B + (size_t)gn0 * ldb + gk) : z;
            pb1 = (kv && gn1 < N) ? *(const float4*)(B + (size_t)gn1 * ldb + gk) : z;
        }
    };
    auto sstore = [&](int buf) {
        As[buf][k4 + 0][r] = pa0.x; As[buf][k4 + 1][r] = pa0.y;
        As[buf][k4 + 2][r] = pa0.z; As[buf][k4 + 3][r] = pa0.w;
        As[buf][k4 + 0][r + 64] = pa1.x; As[buf][k4 + 1][r + 64] = pa1.y;
        As[buf][k4 + 2][r + 64] = pa1.z; As[buf][k4 + 3][r + 64] = pa1.w;
        Bs[buf][k4 + 0][r] = pb0.x; Bs[buf][k4 + 1][r] = pb0.y;
        Bs[buf][k4 + 2][r] = pb0.z; Bs[buf][k4 + 3][r] = pb0.w;
        Bs[buf][k4 + 0][r + 64] = pb1.x; Bs[buf][k4 + 1][r + 64] = pb1.y;
        Bs[buf][k4 + 2][r + 64] = pb1.z; Bs[buf][k4 + 3][r + 64] = pb1.w;
    };

    gload(0);
    sstore(0);
    __syncthreads();

    for (int kt = 0; kt < nk; kt++) {
        const int cur = kt & 1;
        if (kt + 1 < nk) gload(kt + 1);
#pragma unroll
        for (int kk = 0; kk < BK; kk++) {
            float4 a0 = *(const float4*)&As[cur][kk][tm];
            float4 a1 = *(const float4*)&As[cur][kk][tm + 4];
            float4 b0 = *(const float4*)&Bs[cur][kk][tn];
            float4 b1 = *(const float4*)&Bs[cur][kk][tn + 4];
            float ar[8] = {a0.x, a0.y, a0.z, a0.w, a1.x, a1.y, a1.z, a1.w};
            float br[8] = {b0.x, b0.y, b0.z, b0.w, b1.x, b1.y, b1.z, b1.w};
#pragma unroll
            for (int i = 0; i < 8; i++)
#pragma unroll
                for (int j = 0; j < 8; j++)
                    acc[i][j] = fmaf(ar[i], br[j], acc[i][j]);
        }
        if (kt + 1 < nk) {
            sstore(cur ^ 1);
            __syncthreads();
        }
    }

    // epilogue
    float bset[8];
#pragma unroll
    for (int j = 0; j < 8; j++) {
        int col = bn + tn + j;
        bset[j] = (bias && col < N) ? bias[col] : 0.f;
    }
#pragma unroll
    for (int i = 0; i < 8; i++) {
        int row = bm + tm + i;
        if (row >= M) continue;
        float* cp = C + (size_t)row * ldc + bn + tn;
        // cols are 4-aligned vs N (N % 4 == 0), so float4 validity == first-elem validity
        if (bn + tn + 7 < N) {
            float4 v0 = make_float4(acc[i][0] + bset[0], acc[i][1] + bset[1],
                                    acc[i][2] + bset[2], acc[i][3] + bset[3]);
            float4 v1 = make_float4(acc[i][4] + bset[4], acc[i][5] + bset[5],
                                    acc[i][6] + bset[6], acc[i][7] + bset[7]);
            *(float4*)cp = v0;
            *(float4*)(cp + 4) = v1;
        } else {
#pragma unroll
            for (int j = 0; j < 8; j++) {
                int col = bn + tn + j;
                if (col < N) cp[j] = acc[i][j] + bset[j];
            }
        }
    }
}

// ---------------- fused attention: scores -> softmax -> weighted ----------
__global__ __launch_bounds__(256, 1)
void attn_kernel(const float* __restrict__ enc,
                 const float* __restrict__ v,
                 const unsigned char* __restrict__ pad,
                 float* __restrict__ wout, int wstride,
                 float* __restrict__ a_out)
{
    const int b = blockIdx.x;
    const int tid = threadIdx.x;
    const int lane = tid & 31, warp = tid >> 5;
    __shared__ __align__(16) float vsh[ENCD];
    __shared__ float sc[SS];
    __shared__ float red[8];
    const float* encb = enc + (size_t)b * SS * ENCD;

    ((float4*)vsh)[tid] = ((const float4*)(v + (size_t)b * ENCD))[tid];
    __syncthreads();

    const float4* vv = (const float4*)vsh;
    for (int s = warp; s < SS; s += 8) {
        const float4* row = (const float4*)(encb + (size_t)s * ENCD);
        float acc = 0.f;
#pragma unroll
        for (int i = 0; i < ENCD / 128; i++) {
            float4 e4 = row[lane + 32 * i];
            float4 v4 = vv[lane + 32 * i];
            acc = fmaf(e4.x, v4.x, acc);
            acc = fmaf(e4.y, v4.y, acc);
            acc = fmaf(e4.z, v4.z, acc);
            acc = fmaf(e4.w, v4.w, acc);
        }
#pragma unroll
        for (int o = 16; o; o >>= 1) acc += __shfl_xor_sync(0xffffffffu, acc, o);
        if (lane == 0) sc[s] = pad[(size_t)b * SS + s] ? -INFINITY : acc;
    }
    __syncthreads();

    float m = -INFINITY;
    for (int i = tid; i < SS; i += 256) m = fmaxf(m, sc[i]);
#pragma unroll
    for (int o = 16; o; o >>= 1) m = fmaxf(m, __shfl_xor_sync(0xffffffffu, m, o));
    if (lane == 0) red[warp] = m;
    __syncthreads();
    if (tid == 0) {
        float mm = red[0];
        for (int w = 1; w < 8; w++) mm = fmaxf(mm, red[w]);
        red[0] = mm;
    }
    __syncthreads();
    m = red[0];
    __syncthreads();

    float lsum = 0.f;
    for (int i = tid; i < SS; i += 256) {
        float e = __expf(sc[i] - m);
        sc[i] = e;
        lsum += e;
    }
#pragma unroll
    for (int o = 16; o; o >>= 1) lsum += __shfl_xor_sync(0xffffffffu, lsum, o);
    if (lane == 0) red[warp] = lsum;
    __syncthreads();
    if (tid == 0) {
        float t = 0.f;
        for (int w = 0; w < 8; w++) t += red[w];
        red[0] = t;
    }
    __syncthreads();
    float inv = 1.f / red[0];
    for (int i = tid; i < SS; i += 256) {
        float a = sc[i] * inv;
        sc[i] = a;
        if (a_out) a_out[(size_t)b * SS + i] = a;
    }
    __syncthreads();

    const int e0 = tid * 4;
    float wx = 0.f, wy = 0.f, wz = 0.f, ww = 0.f;
#pragma unroll 4
    for (int s = 0; s < SS; s++) {
        float a = sc[s];
        float4 e4 = *(const float4*)(encb + (size_t)s * ENCD + e0);
        wx = fmaf(a, e4.x, wx);
        wy = fmaf(a, e4.y, wy);
        wz = fmaf(a, e4.z, wz);
        ww = fmaf(a, e4.w, ww);
    }
    *(float4*)(wout + (size_t)b * wstride + e0) = make_float4(wx, wy, wz, ww);
}

// ---------------- small elementwise / glue kernels -------------------------
__global__ void embed_copy(const float* __restrict__ emb)
{
    int i = blockIdx.x * blockDim.x + threadIdx.x;
    if (i < BB * EMBD) {
        int b = i / EMBD, j = i - b * EMBD;
        g_rnn[(size_t)b * RNNK + j] = emb[i];
    }
}

__global__ void gru_combine(const float* __restrict__ h1,
                            float* __restrict__ out_h, int write_out)
{
    int i = blockIdx.x * blockDim.x + threadIdx.x;
    if (i >= BB * DECD) return;
    int b = i / DECD, j = i - b * DECD;
    const float* gx = g_gx + (size_t)b * G3;
    const float* gh = g_gh + (size_t)b * G3;
    float r = 1.f / (1.f + __expf(-(gx[j] + gh[j])));
    float z = 1.f / (1.f + __expf(-(gx[j + DECD] + gh[j + DECD])));
    float n = tanhf(gx[j + 2 * DECD] + r * gh[j + 2 * DECD]);
    float h = (1.f - z) * n + z * h1[i];
    g_hw[(size_t)b * HWK + j] = h;
    if (write_out) out_h[i] = h;
}

__global__ __launch_bounds__(128)
void pgen_kernel(const float* __restrict__ Wp, const float* __restrict__ bp)
{
    int b = blockIdx.x, tid = threadIdx.x;
    int lane = tid & 31, warp = tid >> 5;
    __shared__ float red[4];
    const float* hwb = g_hw + (size_t)b * HWK;
    float acc = 0.f;
    for (int i = tid; i < HWK; i += 128) acc = fmaf(hwb[i], Wp[i], acc);
#pragma unroll
    for (int o = 16; o; o >>= 1) acc += __shfl_xor_sync(0xffffffffu, acc, o);
    if (lane == 0) red[warp] = acc;
    __syncthreads();
    if (tid == 0) {
        float t = red[0] + red[1] + red[2] + red[3] + bp[0];
        g_pgen[b] = 1.f / (1.f + __expf(-t));
    }
}

__global__ __launch_bounds__(256)
void pvocab_kernel(float* __restrict__ pout)
{
    int b = blockIdx.x, tid = threadIdx.x;
    int lane = tid & 31, warp = tid >> 5;
    __shared__ float red[8];
    __shared__ float bc[2];
    const float* lg = g_logits + (size_t)b * VOCAB;

    float m = -INFINITY;
    for (int i = tid; i < VOCAB; i += 256) m = fmaxf(m, lg[i]);
#pragma unroll
    for (int o = 16; o; o >>= 1) m = fmaxf(m, __shfl_xor_sync(0xffffffffu, m, o));
    if (lane == 0) red[warp] = m;
    __syncthreads();
    if (tid == 0) {
        float mm = red[0];
        for (int w = 1; w < 8; w++) mm = fmaxf(mm, red[w]);
        bc[0] = mm;
    }
    __syncthreads();
    m = bc[0];

    float s = 0.f;
    for (int i = tid; i < VOCAB; i += 256) s += __expf(lg[i] - m);
#pragma unroll
    for (int o = 16; o; o >>= 1) s += __shfl_xor_sync(0xffffffffu, s, o);
    if (lane == 0) red[warp] = s;
    __syncthreads();
    if (tid == 0) {
        float t = 0.f;
        for (int w = 0; w < 8; w++) t += red[w];
        bc[1] = t;
    }
    __syncthreads();

    float scale = g_pgen[b] / bc[1];
    float* row = pout + (size_t)b * PVC;
    for (int i = tid; i < VOCAB; i += 256) row[i] = __expf(lg[i] - m) * scale;
    for (int i = VOCAB + tid; i < PVC; i += 256) row[i] = 0.f;
}

__global__ void scatter_kernel(const int* __restrict__ src, float* __restrict__ pout)
{
    int i = blockIdx.x * blockDim.x + threadIdx.x;
    if (i >= BB * SS) return;
    int b = i / SS;
    float val = (1.f - g_pgen[b]) * g_a2[i];
    atomicAdd(pout + (size_t)b * PVC + src[i], val);
}

// ---------------- launch ---------------------------------------------------
extern "C" void kernel_launch(void* const* d_in, const int* in_sizes, int n_in,
                              void* d_out, int out_size)
{
    int off = (n_in >= 16) ? 0 : -1;
    const float* embedded = (const float*)d_in[0];
    const float* enc      = (const float*)d_in[1];
    const float* h1       = (const float*)d_in[2];
    const unsigned char* pad = (const unsigned char*)d_in[3];
    const int*   src      = (const int*)d_in[5 + off];
    const float* W_attn1  = (const float*)d_in[6 + off];
    const float* W_attn2  = (const float*)d_in[7 + off];
    const float* W_ih     = (const float*)d_in[8 + off];
    const float* W_hh     = (const float*)d_in[9 + off];
    const float* b_ih     = (const float*)d_in[10 + off];
    const float* b_hh     = (const float*)d_in[11 + off];
    const float* W_out    = (const float*)d_in[12 + off];
    const float* b_out    = (const float*)d_in[13 + off];
    const float* W_p      = (const float*)d_in[14 + off];
    const float* b_p      = (const float*)d_in[15 + off];
    float* pout = (float*)d_out;

    float *v, *rnn, *gx, *gh, *hw, *logits, *a2;
    cudaGetSymbolAddress((void**)&v, g_v);
    cudaGetSymbolAddress((void**)&rnn, g_rnn);
    cudaGetSymbolAddress((void**)&gx, g_gx);
    cudaGetSymbolAddress((void**)&gh, g_gh);
    cudaGetSymbolAddress((void**)&hw, g_hw);
    cudaGetSymbolAddress((void**)&logits, g_logits);
    cudaGetSymbolAddress((void**)&a2, g_a2);

    // 1. rnn[:, 0:EMB] = embedded
    embed_copy<<<(BB * EMBD + 255) / 256, 256>>>(embedded);
    // 2. gh = h1 @ W_hh^T + b_hh (independent of attention; launched early)
    gemm_warp4<<<dim3((G3 + 31) / 32, BB), 256>>>(h1, DECD, W_hh, DECD, gh, G3,
                                                  b_hh, G3, DECD);
    // 3. v1 = h1 @ W_attn1^T  [128,1024]
    gemm_warp4<<<dim3(ENCD / 32, BB), 256>>>(h1, DECD, W_attn1, DECD, v, ENCD,
                                             nullptr, ENCD, DECD);
    // 4. attn1 -> weighted1 into rnn[:, EMB:]
    attn_kernel<<<BB, 256>>>(enc, v, pad, rnn + EMBD, RNNK, nullptr);
    // 5. gx = rnn @ W_ih^T + b_ih  [128,900]
    gemm_warp4<<<dim3((G3 + 31) / 32, BB), 256>>>(rnn, RNNK, W_ih, RNNK, gx, G3,
                                                  b_ih, G3, RNNK);
    // 6. GRU combine -> hw[:, 0:DEC] (= h_new), output tail if present
    int wtail = (out_size >= BB * PVC + BB * DECD) ? 1 : 0;
    gru_combine<<<(BB * DECD + 255) / 256, 256>>>(h1, pout + (size_t)BB * PVC, wtail);
    // 7. v2 = h_new @ W_attn2^T (A = hw, lda=HWK, K=DEC)
    gemm_warp4<<<dim3(ENCD / 32, BB), 256>>>(hw, HWK, W_attn2, DECD, v, ENCD,
                                             nullptr, ENCD, DECD);
    // 8. attn2 -> weighted2 into hw[:, DEC:], save a2
    attn_kernel<<<BB, 256>>>(enc, v, pad, hw + DECD, HWK, a2);
    // 9. p_gen
    pgen_kernel<<<BB, 128>>>(W_p, b_p);
    // 10. logits = hw @ W_out^T + b_out  [128, 50000] — the big one
    sgemm_big<<<dim3((VOCAB + 127) / 128, 1), 256>>>(hw, HWK, W_out, HWK, logits,
                                                     VOCAB, b_out, BB, VOCAB, HWK);
    // 11. p_out[:, :VOCAB] = p_gen * softmax(logits); ext cols zeroed
    pvocab_kernel<<<BB, 256>>>(pout);
    // 12. scatter-add (1-p_gen)*a2 at source ids
    scatter_kernel<<<(BB * SS + 255) / 256, 256>>>(src, pout);
}

// round 4
// speedup vs baseline: 1.7234x; 1.4067x over previous
#include <cuda_runtime.h>
#include <cuda_bf16.h>
#include <math.h>
#include <stdint.h>

#define BB 128
#define SS 400
#define ENCD 1024
#define DECD 300
#define EMBD 128
#define VOCAB 50000
#define MAXOOV 50
#define PVC (VOCAB + MAXOOV)   /* 50050 */
#define RNNK (EMBD + ENCD)     /* 1152 */
#define HWK (DECD + ENCD)      /* 1324 */
#define G3 (3 * DECD)          /* 900 */

// ---------------- scratch (static device globals; no allocation) ----------
__device__ __align__(256) float g_v[BB * ENCD];
__device__ __align__(256) float g_rnn[BB * RNNK];
__device__ __align__(256) float g_gx[BB * G3];
__device__ __align__(256) float g_gh[BB * G3];
__device__ __align__(256) float g_hw[BB * HWK];
__device__ __align__(256) float g_a2[BB * SS];
__device__ __align__(256) float g_pgen[BB];
__device__ __align__(256) float g_logits[(size_t)BB * VOCAB];

// ======================= helpers ==========================================
__device__ __forceinline__ uint32_t smem_u32(const void* p) {
    uint32_t a;
    asm("{ .reg .u64 t; cvta.to.shared.u64 t, %1; cvt.u32.u64 %0, t; }"
        : "=r"(a) : "l"(p));
    return a;
}

__device__ __forceinline__ void ldmx4(uint32_t* r, uint32_t addr) {
    asm volatile("ldmatrix.sync.aligned.m8n8.x4.shared.b16 {%0,%1,%2,%3}, [%4];"
                 : "=r"(r[0]), "=r"(r[1]), "=r"(r[2]), "=r"(r[3]) : "r"(addr));
}

__device__ __forceinline__ void mma16816(float* d, const uint32_t* a,
                                         uint32_t b0, uint32_t b1) {
    asm volatile(
        "mma.sync.aligned.m16n8k16.row.col.f32.bf16.bf16.f32 "
        "{%0,%1,%2,%3}, {%4,%5,%6,%7}, {%8,%9}, {%0,%1,%2,%3};"
        : "+f"(d[0]), "+f"(d[1]), "+f"(d[2]), "+f"(d[3])
        : "r"(a[0]), "r"(a[1]), "r"(a[2]), "r"(a[3]), "r"(b0), "r"(b1));
}

// fp32x4 -> bf16 hi + lo (residual) packed stores (4 halves each)
__device__ __forceinline__ void cvt_store_pair(__nv_bfloat16* hi,
                                               __nv_bfloat16* lo, float4 v) {
    __nv_bfloat16 h0 = __float2bfloat16(v.x);
    __nv_bfloat16 h1 = __float2bfloat16(v.y);
    __nv_bfloat16 h2 = __float2bfloat16(v.z);
    __nv_bfloat16 h3 = __float2bfloat16(v.w);
    __nv_bfloat16 l0 = __float2bfloat16(v.x - __bfloat162float(h0));
    __nv_bfloat16 l1 = __float2bfloat16(v.y - __bfloat162float(h1));
    __nv_bfloat16 l2 = __float2bfloat16(v.z - __bfloat162float(h2));
    __nv_bfloat16 l3 = __float2bfloat16(v.w - __bfloat162float(h3));
    uint32_t hA = (uint32_t)__bfloat16_as_ushort(h0) | ((uint32_t)__bfloat16_as_ushort(h1) << 16);
    uint32_t hB = (uint32_t)__bfloat16_as_ushort(h2) | ((uint32_t)__bfloat16_as_ushort(h3) << 16);
    uint32_t lA = (uint32_t)__bfloat16_as_ushort(l0) | ((uint32_t)__bfloat16_as_ushort(l1) << 16);
    uint32_t lB = (uint32_t)__bfloat16_as_ushort(l2) | ((uint32_t)__bfloat16_as_ushort(l3) << 16);
    *(uint2*)hi = make_uint2(hA, hB);
    *(uint2*)lo = make_uint2(lA, lB);
}

// ====================================================================
// Tensor-core logits GEMM via mma.sync (sm_80 baseline ISA — works on
// .target sm_100): C[128, N] = A[128,K] * B[N,K]^T + bias.
// fp32 operands split to bf16 hi+lo in-flight; 3 MMAs (hh, hl, lh) give
// ~2^-17 relative error. 128x128 CTA tile, K chunks of 32, double-
// buffered smem, 8 warps x (64x32) microtiles, m16n8k16 fragments.
// ====================================================================
#define CH 32
#define NCH ((HWK + CH - 1) / CH)   /* 42 */
#define ASTRIDE 40                  /* halves per smem row (conflict-free, 16B-aligned) */
#define ARR_B (128 * ASTRIDE * 2)   /* 10240 bytes per array */
#define BUF_B (4 * ARR_B)           /* Ahi,Alo,Bhi,Blo = 40960 */
#define MM_SMEM (2 * BUF_B)         /* 81920 */

__global__ __launch_bounds__(256, 2)
void gemm_mma(const float* __restrict__ A, int lda,
              const float* __restrict__ B, int ldb,
              float* __restrict__ C, int ldc,
              const float* __restrict__ bias, int N, int K)
{
    extern __shared__ char smem[];
    const uint32_t sbase = smem_u32(smem);
    const int tid = threadIdx.x;
    const int wid = tid >> 5, lid = tid & 31;
    const int warp_m = (wid >> 2) * 64;   // 0, 64
    const int warp_n = (wid & 3) * 32;    // 0..96
    const int bn = blockIdx.x * 128;

    float acc[4][4][4] = {};

    auto load_chunk = [&](int c, int buf) {
        char* base = smem + buf * BUF_B;
        __nv_bfloat16* Ah = (__nv_bfloat16*)(base);
        __nv_bfloat16* Al = (__nv_bfloat16*)(base + ARR_B);
        __nv_bfloat16* Bh = (__nv_bfloat16*)(base + 2 * ARR_B);
        __nv_bfloat16* Bl = (__nv_bfloat16*)(base + 3 * ARR_B);
        const int kb = c * CH;
#pragma unroll
        for (int t = 0; t < 4; t++) {
            int idx = tid + t * 256;      // 0..1023
            int row = idx >> 3;           // 0..127
            int c4  = (idx & 7) << 2;     // 0..28
            int gk = kb + c4;
            float4 va = make_float4(0.f, 0.f, 0.f, 0.f);
            float4 vb = va;
            if (gk < K) {                 // K % 4 == 0 -> float4-granular
                va = *(const float4*)(A + (size_t)row * lda + gk);
                int n = bn + row;
                if (n < N) vb = *(const float4*)(B + (size_t)n * ldb + gk);
            }
            int so = row * ASTRIDE + c4;
            cvt_store_pair(Ah + so, Al + so, va);
            cvt_store_pair(Bh + so, Bl + so, vb);
        }
    };

    auto compute_chunk = [&](int buf) {
        const uint32_t base = sbase + buf * BUF_B;
        const uint32_t Ah = base, Al = base + ARR_B;
        const uint32_t Bh = base + 2 * ARR_B, Bl = base + 3 * ARR_B;
        const int lrow = lid & 15;
        const int lcol = (lid >> 4) << 3;
#pragma unroll
        for (int kk = 0; kk < CH; kk += 16) {
            // B fragments: two x4 loads cover 4 n8-frags (hi and lo)
            uint32_t bh0[4], bl0[4], bh1[4], bl1[4];
            {
                uint32_t o0 = (uint32_t)(((warp_n + 0  + lrow) * ASTRIDE + kk + lcol) * 2);
                uint32_t o1 = (uint32_t)(((warp_n + 16 + lrow) * ASTRIDE + kk + lcol) * 2);
                ldmx4(bh0, Bh + o0); ldmx4(bl0, Bl + o0);
                ldmx4(bh1, Bh + o1); ldmx4(bl1, Bl + o1);
            }
#pragma unroll
            for (int fm = 0; fm < 4; fm++) {
                uint32_t ah[4], al[4];
                uint32_t ao = (uint32_t)(((warp_m + fm * 16 + lrow) * ASTRIDE + kk + lcol) * 2);
                ldmx4(ah, Ah + ao);
                ldmx4(al, Al + ao);
                // fn0: {bh0[0],bh0[2]}  fn1: {bh0[1],bh0[3]}
                // fn2: {bh1[0],bh1[2]}  fn3: {bh1[1],bh1[3]}
                mma16816(acc[fm][0], ah, bh0[0], bh0[2]);
                mma16816(acc[fm][0], ah, bl0[0], bl0[2]);
                mma16816(acc[fm][0], al, bh0[0], bh0[2]);
                mma16816(acc[fm][1], ah, bh0[1], bh0[3]);
                mma16816(acc[fm][1], ah, bl0[1], bl0[3]);
                mma16816(acc[fm][1], al, bh0[1], bh0[3]);
                mma16816(acc[fm][2], ah, bh1[0], bh1[2]);
                mma16816(acc[fm][2], ah, bl1[0], bl1[2]);
                mma16816(acc[fm][2], al, bh1[0], bh1[2]);
                mma16816(acc[fm][3], ah, bh1[1], bh1[3]);
                mma16816(acc[fm][3], ah, bl1[1], bl1[3]);
                mma16816(acc[fm][3], al, bh1[1], bh1[3]);
            }
        }
    };

    load_chunk(0, 0);
    __syncthreads();
    for (int c = 0; c < NCH; c++) {
        if (c + 1 < NCH) load_chunk(c + 1, (c + 1) & 1);
        compute_chunk(c & 1);
        __syncthreads();
    }

    // epilogue: d frag thread mapping (t/4 = row-in-8, 2*(t%4) = col pair)
    const int erow = lid >> 2;
    const int ecol = (lid & 3) << 1;
#pragma unroll
    for (int fm = 0; fm < 4; fm++) {
#pragma unroll
        for (int fn = 0; fn < 4; fn++) {
            int row = warp_m + fm * 16 + erow;
            int col = bn + warp_n + fn * 8 + ecol;
            if (col < N) {     // col even, N even -> col+1 < N too
                float b0 = bias[col], b1 = bias[col + 1];
                float* d = acc[fm][fn];
                *(float2*)(C + (size_t)row * ldc + col) =
                    make_float2(d[0] + b0, d[1] + b1);
                *(float2*)(C + (size_t)(row + 8) * ldc + col) =
                    make_float2(d[2] + b0, d[3] + b1);
            }
        }
    }
}

// ====================================================================
// Small-GEMM path: C[M,N] = A[M,K] * B[N,K]^T (+bias).
// ====================================================================
__global__ __launch_bounds__(256)
void gemm_warp4(const float* __restrict__ A, int lda,
                const float* __restrict__ B, int ldb,
                float* __restrict__ C, int ldc,
                const float* __restrict__ bias, int N, int K)
{
    const int m = blockIdx.y;
    const int warp = threadIdx.x >> 5, lane = threadIdx.x & 31;
    const int n0 = blockIdx.x * 32 + warp * 4;
    if (n0 >= N) return;
    const float4* a = (const float4*)(A + (size_t)m * lda);
    const float4* b0 = (const float4*)(B + (size_t)(n0 + 0) * ldb);
    const float4* b1 = (const float4*)(B + (size_t)(n0 + 1) * ldb);
    const float4* b2 = (const float4*)(B + (size_t)(n0 + 2) * ldb);
    const float4* b3 = (const float4*)(B + (size_t)(n0 + 3) * ldb);
    const int K4 = K >> 2;
    float acc0 = 0.f, acc1 = 0.f, acc2 = 0.f, acc3 = 0.f;
    for (int i = lane; i < K4; i += 32) {
        float4 av = a[i];
        float4 v0 = b0[i], v1 = b1[i], v2 = b2[i], v3 = b3[i];
        acc0 = fmaf(av.x, v0.x, fmaf(av.y, v0.y, fmaf(av.z, v0.z, fmaf(av.w, v0.w, acc0))));
        acc1 = fmaf(av.x, v1.x, fmaf(av.y, v1.y, fmaf(av.z, v1.z, fmaf(av.w, v1.w, acc1))));
        acc2 = fmaf(av.x, v2.x, fmaf(av.y, v2.y, fmaf(av.z, v2.z, fmaf(av.w, v2.w, acc2))));
        acc3 = fmaf(av.x, v3.x, fmaf(av.y, v3.y, fmaf(av.z, v3.z, fmaf(av.w, v3.w, acc3))));
    }
#pragma unroll
    for (int o = 16; o; o >>= 1) {
        acc0 += __shfl_xor_sync(0xffffffffu, acc0, o);
        acc1 += __shfl_xor_sync(0xffffffffu, acc1, o);
        acc2 += __shfl_xor_sync(0xffffffffu, acc2, o);
        acc3 += __shfl_xor_sync(0xffffffffu, acc3, o);
    }
    if (lane == 0) {
        float* c = C + (size_t)m * ldc + n0;
        if (bias) {
            c[0] = acc0 + bias[n0 + 0];
            c[1] = acc1 + bias[n0 + 1];
            c[2] = acc2 + bias[n0 + 2];
            c[3] = acc3 + bias[n0 + 3];
        } else {
            c[0] = acc0; c[1] = acc1; c[2] = acc2; c[3] = acc3;
        }
    }
}

// ---------------- fused attention: scores -> softmax -> weighted ----------
// 1024 threads/block (32 warps) for latency hiding. block per batch row.
__global__ __launch_bounds__(1024, 1)
void attn_kernel(const float* __restrict__ enc,
                 const float* __restrict__ v,
                 const unsigned char* __restrict__ pad,
                 float* __restrict__ wout, int wstride,
                 float* __restrict__ a_out)
{
    const int b = blockIdx.x;
    const int tid = threadIdx.x;
    const int lane = tid & 31, warp = tid >> 5;
    __shared__ __align__(16) float vsh[ENCD];
    __shared__ float sc[SS];
    __shared__ float red[32];
    const float* encb = enc + (size_t)b * SS * ENCD;

    if (tid < ENCD / 4)
        ((float4*)vsh)[tid] = ((const float4*)(v + (size_t)b * ENCD))[tid];
    __syncthreads();

    const float4* vv = (const float4*)vsh;
    for (int s = warp; s < SS; s += 32) {
        const float4* row = (const float4*)(encb + (size_t)s * ENCD);
        float acc = 0.f;
#pragma unroll
        for (int i = 0; i < ENCD / 128; i++) {
            float4 e4 = row[lane + 32 * i];
            float4 v4 = vv[lane + 32 * i];
            acc = fmaf(e4.x, v4.x, acc);
            acc = fmaf(e4.y, v4.y, acc);
            acc = fmaf(e4.z, v4.z, acc);
            acc = fmaf(e4.w, v4.w, acc);
        }
#pragma unroll
        for (int o = 16; o; o >>= 1) acc += __shfl_xor_sync(0xffffffffu, acc, o);
        if (lane == 0) sc[s] = pad[(size_t)b * SS + s] ? -INFINITY : acc;
    }
    __syncthreads();

    float m = -INFINITY;
    for (int i = tid; i < SS; i += 1024) m = fmaxf(m, sc[i]);
#pragma unroll
    for (int o = 16; o; o >>= 1) m = fmaxf(m, __shfl_xor_sync(0xffffffffu, m, o));
    if (lane == 0) red[warp] = m;
    __syncthreads();
    if (tid == 0) {
        float mm = red[0];
        for (int w = 1; w < 32; w++) mm = fmaxf(mm, red[w]);
        red[0] = mm;
    }
    __syncthreads();
    m = red[0];
    __syncthreads();

    float lsum = 0.f;
    for (int i = tid; i < SS; i += 1024) {
        float e = __expf(sc[i] - m);
        sc[i] = e;
        lsum += e;
    }
#pragma unroll
    for (int o = 16; o; o >>= 1) lsum += __shfl_xor_sync(0xffffffffu, lsum, o);
    if (lane == 0) red[warp] = lsum;
    __syncthreads();
    if (tid == 0) {
        float t = 0.f;
        for (int w = 0; w < 32; w++) t += red[w];
        red[0] = t;
    }
    __syncthreads();
    float inv = 1.f / red[0];
    for (int i = tid; i < SS; i += 1024) {
        float a = sc[i] * inv;
        sc[i] = a;
        if (a_out) a_out[(size_t)b * SS + i] = a;
    }
    __syncthreads();

    // weighted[b, e] = sum_s a[s] * enc[b,s,e]; thread per column
    const int e = tid;
    float w0 = 0.f, w1 = 0.f, w2 = 0.f, w3 = 0.f;
    const float* p = encb + e;
#pragma unroll 1
    for (int s = 0; s < SS; s += 4) {
        w0 = fmaf(sc[s + 0], p[(size_t)(s + 0) * ENCD], w0);
        w1 = fmaf(sc[s + 1], p[(size_t)(s + 1) * ENCD], w1);
        w2 = fmaf(sc[s + 2], p[(size_t)(s + 2) * ENCD], w2);
        w3 = fmaf(sc[s + 3], p[(size_t)(s + 3) * ENCD], w3);
    }
    wout[(size_t)b * wstride + e] = (w0 + w1) + (w2 + w3);
}

// ---------------- small elementwise / glue kernels -------------------------
__global__ void embed_copy(const float* __restrict__ emb)
{
    int i = blockIdx.x * blockDim.x + threadIdx.x;
    if (i < BB * EMBD) {
        int b = i / EMBD, j = i - b * EMBD;
        g_rnn[(size_t)b * RNNK + j] = emb[i];
    }
}

__global__ void gru_combine(const float* __restrict__ h1,
                            float* __restrict__ out_h, int write_out)
{
    int i = blockIdx.x * blockDim.x + threadIdx.x;
    if (i >= BB * DECD) return;
    int b = i / DECD, j = i - b * DECD;
    const float* gx = g_gx + (size_t)b * G3;
    const float* gh = g_gh + (size_t)b * G3;
    float r = 1.f / (1.f + __expf(-(gx[j] + gh[j])));
    float z = 1.f / (1.f + __expf(-(gx[j + DECD] + gh[j + DECD])));
    float n = tanhf(gx[j + 2 * DECD] + r * gh[j + 2 * DECD]);
    float h = (1.f - z) * n + z * h1[i];
    g_hw[(size_t)b * HWK + j] = h;
    if (write_out) out_h[i] = h;
}

__global__ __launch_bounds__(128)
void pgen_kernel(const float* __restrict__ Wp, const float* __restrict__ bp)
{
    int b = blockIdx.x, tid = threadIdx.x;
    int lane = tid & 31, warp = tid >> 5;
    __shared__ float red[4];
    const float* hwb = g_hw + (size_t)b * HWK;
    float acc = 0.f;
    for (int i = tid; i < HWK; i += 128) acc = fmaf(hwb[i], Wp[i], acc);
#pragma unroll
    for (int o = 16; o; o >>= 1) acc += __shfl_xor_sync(0xffffffffu, acc, o);
    if (lane == 0) red[warp] = acc;
    __syncthreads();
    if (tid == 0) {
        float t = red[0] + red[1] + red[2] + red[3] + bp[0];
        g_pgen[b] = 1.f / (1.f + __expf(-t));
    }
}

__global__ __launch_bounds__(256)
void pvocab_kernel(float* __restrict__ pout)
{
    int b = blockIdx.x, tid = threadIdx.x;
    int lane = tid & 31, warp = tid >> 5;
    __shared__ float red[8];
    __shared__ float bc[2];
    const float* lg = g_logits + (size_t)b * VOCAB;

    float m = -INFINITY;
    for (int i = tid; i < VOCAB; i += 256) m = fmaxf(m, lg[i]);
#pragma unroll
    for (int o = 16; o; o >>= 1) m = fmaxf(m, __shfl_xor_sync(0xffffffffu, m, o));
    if (lane == 0) red[warp] = m;
    __syncthreads();
    if (tid == 0) {
        float mm = red[0];
        for (int w = 1; w < 8; w++) mm = fmaxf(mm, red[w]);
        bc[0] = mm;
    }
    __syncthreads();
    m = bc[0];

    float s = 0.f;
    for (int i = tid; i < VOCAB; i += 256) s += __expf(lg[i] - m);
#pragma unroll
    for (int o = 16; o; o >>= 1) s += __shfl_xor_sync(0xffffffffu, s, o);
    if (lane == 0) red[warp] = s;
    __syncthreads();
    if (tid == 0) {
        float t = 0.f;
        for (int w = 0; w < 8; w++) t += red[w];
        bc[1] = t;
    }
    __syncthreads();

    float scale = g_pgen[b] / bc[1];
    float* row = pout + (size_t)b * PVC;
    for (int i = tid; i < VOCAB; i += 256) row[i] = __expf(lg[i] - m) * scale;
    for (int i = VOCAB + tid; i < PVC; i += 256) row[i] = 0.f;
}

__global__ void scatter_kernel(const int* __restrict__ src, float* __restrict__ pout)
{
    int i = blockIdx.x * blockDim.x + threadIdx.x;
    if (i >= BB * SS) return;
    int b = i / SS;
    float val = (1.f - g_pgen[b]) * g_a2[i];
    atomicAdd(pout + (size_t)b * PVC + src[i], val);
}

// ---------------- launch ---------------------------------------------------
extern "C" void kernel_launch(void* const* d_in, const int* in_sizes, int n_in,
                              void* d_out, int out_size)
{
    int off = (n_in >= 16) ? 0 : -1;
    const float* embedded = (const float*)d_in[0];
    const float* enc      = (const float*)d_in[1];
    const float* h1       = (const float*)d_in[2];
    const unsigned char* pad = (const unsigned char*)d_in[3];
    const int*   src      = (const int*)d_in[5 + off];
    const float* W_attn1  = (const float*)d_in[6 + off];
    const float* W_attn2  = (const float*)d_in[7 + off];
    const float* W_ih     = (const float*)d_in[8 + off];
    const float* W_hh     = (const float*)d_in[9 + off];
    const float* b_ih     = (const float*)d_in[10 + off];
    const float* b_hh     = (const float*)d_in[11 + off];
    const float* W_out    = (const float*)d_in[12 + off];
    const float* b_out    = (const float*)d_in[13 + off];
    const float* W_p      = (const float*)d_in[14 + off];
    const float* b_p      = (const float*)d_in[15 + off];
    float* pout = (float*)d_out;

    float *v, *rnn, *gx, *gh, *hw, *logits, *a2;
    cudaGetSymbolAddress((void**)&v, g_v);
    cudaGetSymbolAddress((void**)&rnn, g_rnn);
    cudaGetSymbolAddress((void**)&gx, g_gx);
    cudaGetSymbolAddress((void**)&gh, g_gh);
    cudaGetSymbolAddress((void**)&hw, g_hw);
    cudaGetSymbolAddress((void**)&logits, g_logits);
    cudaGetSymbolAddress((void**)&a2, g_a2);

    cudaFuncSetAttribute(gemm_mma, cudaFuncAttributeMaxDynamicSharedMemorySize, MM_SMEM);

    // 1. rnn[:, 0:EMB] = embedded
    embed_copy<<<(BB * EMBD + 255) / 256, 256>>>(embedded);
    // 2. gh = h1 @ W_hh^T + b_hh
    gemm_warp4<<<dim3((G3 + 31) / 32, BB), 256>>>(h1, DECD, W_hh, DECD, gh, G3,
                                                  b_hh, G3, DECD);
    // 3. v1 = h1 @ W_attn1^T
    gemm_warp4<<<dim3(ENCD / 32, BB), 256>>>(h1, DECD, W_attn1, DECD, v, ENCD,
                                             nullptr, ENCD, DECD);
    // 4. attn1 -> weighted1 into rnn[:, EMB:]
    attn_kernel<<<BB, 1024>>>(enc, v, pad, rnn + EMBD, RNNK, nullptr);
    // 5. gx = rnn @ W_ih^T + b_ih
    gemm_warp4<<<dim3((G3 + 31) / 32, BB), 256>>>(rnn, RNNK, W_ih, RNNK, gx, G3,
                                                  b_ih, G3, RNNK);
    // 6. GRU combine -> hw[:, 0:DEC] (= h_new)
    int wtail = (out_size >= BB * PVC + BB * DECD) ? 1 : 0;
    gru_combine<<<(BB * DECD + 255) / 256, 256>>>(h1, pout + (size_t)BB * PVC, wtail);
    // 7. v2 = h_new @ W_attn2^T
    gemm_warp4<<<dim3(ENCD / 32, BB), 256>>>(hw, HWK, W_attn2, DECD, v, ENCD,
                                             nullptr, ENCD, DECD);
    // 8. attn2 -> weighted2 into hw[:, DEC:], save a2
    attn_kernel<<<BB, 1024>>>(enc, v, pad, hw + DECD, HWK, a2);
    // 9. p_gen
    pgen_kernel<<<BB, 128>>>(W_p, b_p);
    // 10. logits = hw @ W_out^T + b_out — mma.sync bf16 hi/lo split
    gemm_mma<<<dim3((VOCAB + 127) / 128), 256, MM_SMEM>>>(hw, HWK, W_out, HWK,
                                                          logits, VOCAB, b_out,
                                                          VOCAB, HWK);
    // 11. p_out[:, :VOCAB] = p_gen * softmax(logits); ext cols zeroed
    pvocab_kernel<<<BB, 256>>>(pout);
    // 12. scatter-add (1-p_gen)*a2 at source ids
    scatter_kernel<<<(BB * SS + 255) / 256, 256>>>(src, pout);
}

// round 6
// speedup vs baseline: 2.3831x; 1.3828x over previous
#include <cuda_runtime.h>
#include <cuda_bf16.h>
#include <math.h>
#include <stdint.h>

#define BB 128
#define SS 400
#define ENCD 1024
#define DECD 300
#define EMBD 128
#define VOCAB 50000
#define MAXOOV 50
#define PVC (VOCAB + MAXOOV)   /* 50050 */
#define RNNK (EMBD + ENCD)     /* 1152 */
#define HWK (DECD + ENCD)      /* 1324 */
#define G3 (3 * DECD)          /* 900 */
#define KPAD 1344              /* HWK padded to multiple of 32 */

// ---------------- scratch (static device globals; no allocation) ----------
__device__ __align__(256) float g_v[BB * ENCD];
__device__ __align__(256) float g_rnn[BB * RNNK];
__device__ __align__(256) float g_gx[BB * G3];
__device__ __align__(256) float g_gh[BB * G3];
__device__ __align__(256) float g_hw[BB * HWK];
__device__ __align__(256) float g_sc[BB * SS];
__device__ __align__(256) float g_a2[BB * SS];
__device__ __align__(256) float g_pgen[BB];
__device__ __align__(256) float g_logits[(size_t)BB * VOCAB];
__device__ __align__(256) __nv_bfloat16 g_Ah[BB * KPAD];
__device__ __align__(256) __nv_bfloat16 g_Al[BB * KPAD];

// ======================= helpers ==========================================
__device__ __forceinline__ uint32_t smem_u32(const void* p) {
    uint32_t a;
    asm("{ .reg .u64 t; cvta.to.shared.u64 t, %1; cvt.u32.u64 %0, t; }"
        : "=r"(a) : "l"(p));
    return a;
}

__device__ __forceinline__ void ldmx4(uint32_t* r, uint32_t addr) {
    asm volatile("ldmatrix.sync.aligned.m8n8.x4.shared.b16 {%0,%1,%2,%3}, [%4];"
                 : "=r"(r[0]), "=r"(r[1]), "=r"(r[2]), "=r"(r[3]) : "r"(addr));
}

__device__ __forceinline__ void mma16816(float* d, const uint32_t* a,
                                         uint32_t b0, uint32_t b1) {
    asm volatile(
        "mma.sync.aligned.m16n8k16.row.col.f32.bf16.bf16.f32 "
        "{%0,%1,%2,%3}, {%4,%5,%6,%7}, {%8,%9}, {%0,%1,%2,%3};"
        : "+f"(d[0]), "+f"(d[1]), "+f"(d[2]), "+f"(d[3])
        : "r"(a[0]), "r"(a[1]), "r"(a[2]), "r"(a[3]), "r"(b0), "r"(b1));
}

__device__ __forceinline__ void cp16(uint32_t dst, const void* src) {
    asm volatile("cp.async.cg.shared.global [%0], [%1], 16;"
                 :: "r"(dst), "l"(src) : "memory");
}
__device__ __forceinline__ void cp_commit() {
    asm volatile("cp.async.commit_group;" ::: "memory");
}
__device__ __forceinline__ void cp_wait0() {
    asm volatile("cp.async.wait_group 0;" ::: "memory");
}

// fp32x4 -> bf16 hi + lo (residual) packed stores (4 halves each)
__device__ __forceinline__ void cvt_store_pair(__nv_bfloat16* hi,
                                               __nv_bfloat16* lo, float4 v) {
    __nv_bfloat16 h0 = __float2bfloat16(v.x);
    __nv_bfloat16 h1 = __float2bfloat16(v.y);
    __nv_bfloat16 h2 = __float2bfloat16(v.z);
    __nv_bfloat16 h3 = __float2bfloat16(v.w);
    __nv_bfloat16 l0 = __float2bfloat16(v.x - __bfloat162float(h0));
    __nv_bfloat16 l1 = __float2bfloat16(v.y - __bfloat162float(h1));
    __nv_bfloat16 l2 = __float2bfloat16(v.z - __bfloat162float(h2));
    __nv_bfloat16 l3 = __float2bfloat16(v.w - __bfloat162float(h3));
    uint32_t hA = (uint32_t)__bfloat16_as_ushort(h0) | ((uint32_t)__bfloat16_as_ushort(h1) << 16);
    uint32_t hB = (uint32_t)__bfloat16_as_ushort(h2) | ((uint32_t)__bfloat16_as_ushort(h3) << 16);
    uint32_t lA = (uint32_t)__bfloat16_as_ushort(l0) | ((uint32_t)__bfloat16_as_ushort(l1) << 16);
    uint32_t lB = (uint32_t)__bfloat16_as_ushort(l2) | ((uint32_t)__bfloat16_as_ushort(l3) << 16);
    *(uint2*)hi = make_uint2(hA, hB);
    *(uint2*)lo = make_uint2(lA, lB);
}

// convert A (g_hw fp32) -> g_Ah/g_Al bf16, zero-padded to KPAD
__global__ void convA_kernel()
{
    int b = blockIdx.x;
    for (int k = threadIdx.x; k < KPAD; k += blockDim.x) {
        float x = (k < HWK) ? g_hw[(size_t)b * HWK + k] : 0.f;
        __nv_bfloat16 h = __float2bfloat16(x);
        g_Ah[(size_t)b * KPAD + k] = h;
        g_Al[(size_t)b * KPAD + k] = __float2bfloat16(x - __bfloat162float(h));
    }
}

// ====================================================================
// Tensor-core logits GEMM via mma.sync: C[128,N] = A[128,K]*B[N,K]^T + bias.
// A pre-converted to bf16 hi/lo in global (cp.async path, no in-loop cvt).
// B LDG-staged in regs BEFORE compute, converted+STS AFTER compute.
// 3 MMAs (hh, hl, lh) per fragment for ~fp32 accuracy.
// ====================================================================
#define CH 32
#define NCH (KPAD / CH)             /* 42 */
#define ASTRIDE 40                  /* halves per smem row */
#define ARR_B (128 * ASTRIDE * 2)   /* 10240 bytes per array */
#define BUF_B (4 * ARR_B)           /* Ahi,Alo,Bhi,Blo = 40960 */
#define MM_SMEM (2 * BUF_B)         /* 81920 */

__global__ __launch_bounds__(256, 1)
void gemm_mma(const float* __restrict__ B, int ldb,
              float* __restrict__ C, int ldc,
              const float* __restrict__ bias, int N, int K)
{
    extern __shared__ char smem[];
    const uint32_t sbase = smem_u32(smem);
    const int tid = threadIdx.x;
    const int wid = tid >> 5, lid = tid & 31;
    const int warp_m = (wid >> 2) * 64;   // 0, 64
    const int warp_n = (wid & 3) * 32;    // 0..96
    const int bn = blockIdx.x * 128;

    float acc[4][4][4] = {};
    float4 stB[4];

    // cp.async A tiles (already bf16 in global)
    const int a_arr = tid >> 7;           // 0 = hi, 1 = lo
    const int a_row = tid & 127;
    const __nv_bfloat16* a_src_base = a_arr ? g_Al : g_Ah;
    auto cpA = [&](int c, int buf) {
        uint32_t dst = sbase + buf * BUF_B + a_arr * ARR_B + a_row * (ASTRIDE * 2);
        const char* src = (const char*)(a_src_base + (size_t)a_row * KPAD + c * CH);
#pragma unroll
        for (int j = 0; j < 4; j++) cp16(dst + j * 16, src + j * 16);
    };

    auto ldgB = [&](int c) {
        const int kb = c * CH;
#pragma unroll
        for (int t = 0; t < 4; t++) {
            int idx = tid + t * 256;
            int row = idx >> 3;
            int c4 = (idx & 7) << 2;
            int gk = kb + c4;
            float4 v = make_float4(0.f, 0.f, 0.f, 0.f);
            if (gk < K) {                 // K % 4 == 0
                int n = bn + row;
                if (n < N) v = *(const float4*)(B + (size_t)n * ldb + gk);
            }
            stB[t] = v;
        }
    };
    auto stsB = [&](int buf) {
        char* base = smem + buf * BUF_B + 2 * ARR_B;
        __nv_bfloat16* Bh = (__nv_bfloat16*)base;
        __nv_bfloat16* Bl = (__nv_bfloat16*)(base + ARR_B);
#pragma unroll
        for (int t = 0; t < 4; t++) {
            int idx = tid + t * 256;
            int row = idx >> 3;
            int c4 = (idx & 7) << 2;
            int so = row * ASTRIDE + c4;
            cvt_store_pair(Bh + so, Bl + so, stB[t]);
        }
    };

    auto compute_chunk = [&](int buf) {
        const uint32_t base = sbase + buf * BUF_B;
        const uint32_t Ah = base, Al = base + ARR_B;
        const uint32_t Bh = base + 2 * ARR_B, Bl = base + 3 * ARR_B;
        const int lrow = lid & 15;
        const int lcol = (lid >> 4) << 3;
#pragma unroll
        for (int kk = 0; kk < CH; kk += 16) {
            uint32_t bh0[4], bl0[4], bh1[4], bl1[4];
            {
                uint32_t o0 = (uint32_t)(((warp_n + 0  + lrow) * ASTRIDE + kk + lcol) * 2);
                uint32_t o1 = (uint32_t)(((warp_n + 16 + lrow) * ASTRIDE + kk + lcol) * 2);
                ldmx4(bh0, Bh + o0); ldmx4(bl0, Bl + o0);
                ldmx4(bh1, Bh + o1); ldmx4(bl1, Bl + o1);
            }
#pragma unroll
            for (int fm = 0; fm < 4; fm++) {
                uint32_t ah[4], al[4];
                uint32_t ao = (uint32_t)(((warp_m + fm * 16 + lrow) * ASTRIDE + kk + lcol) * 2);
                ldmx4(ah, Ah + ao);
                ldmx4(al, Al + ao);
                mma16816(acc[fm][0], ah, bh0[0], bh0[2]);
                mma16816(acc[fm][0], ah, bl0[0], bl0[2]);
                mma16816(acc[fm][0], al, bh0[0], bh0[2]);
                mma16816(acc[fm][1], ah, bh0[1], bh0[3]);
                mma16816(acc[fm][1], ah, bl0[1], bl0[3]);
                mma16816(acc[fm][1], al, bh0[1], bh0[3]);
                mma16816(acc[fm][2], ah, bh1[0], bh1[2]);
                mma16816(acc[fm][2], ah, bl1[0], bl1[2]);
                mma16816(acc[fm][2], al, bh1[0], bh1[2]);
                mma16816(acc[fm][3], ah, bh1[1], bh1[3]);
                mma16816(acc[fm][3], ah, bl1[1], bl1[3]);
                mma16816(acc[fm][3], al, bh1[1], bh1[3]);
            }
        }
    };

    // prologue
    cpA(0, 0); cp_commit();
    ldgB(0);
    stsB(0);
    cp_wait0();
    __syncthreads();

    for (int c = 0; c < NCH; c++) {
        const int buf = c & 1, nb = buf ^ 1;
        if (c + 1 < NCH) {
            cpA(c + 1, nb); cp_commit();
            ldgB(c + 1);              // LDG issued; latency hidden by MMAs
        }
        compute_chunk(buf);
        if (c + 1 < NCH) {
            stsB(nb);
            cp_wait0();
        }
        __syncthreads();
    }

    // epilogue
    const int erow = lid >> 2;
    const int ecol = (lid & 3) << 1;
#pragma unroll
    for (int fm = 0; fm < 4; fm++) {
#pragma unroll
        for (int fn = 0; fn < 4; fn++) {
            int row = warp_m + fm * 16 + erow;
            int col = bn + warp_n + fn * 8 + ecol;
            if (col < N) {
                float b0 = bias[col], b1 = bias[col + 1];
                float* d = acc[fm][fn];
                *(float2*)(C + (size_t)row * ldc + col) =
                    make_float2(d[0] + b0, d[1] + b1);
                *(float2*)(C + (size_t)(row + 8) * ldc + col) =
                    make_float2(d[2] + b0, d[3] + b1);
            }
        }
    }
}

// ====================================================================
// Small-GEMM: C[M,N] = A[M,K]*B[N,K]^T (+bias). Warp computes 8 m-rows
// x 4 n-cols (B loads reused 8x). grid = (ceil(N/32), M/8), 256 thr.
// ====================================================================
__global__ __launch_bounds__(256)
void gemm_warp8m(const float* __restrict__ A, int lda,
                 const float* __restrict__ B, int ldb,
                 float* __restrict__ C, int ldc,
                 const float* __restrict__ bias, int N, int K)
{
    const int m0 = blockIdx.y * 8;
    const int warp = threadIdx.x >> 5, lane = threadIdx.x & 31;
    const int n0 = blockIdx.x * 32 + warp * 4;
    if (n0 >= N) return;
    const float4* b0 = (const float4*)(B + (size_t)(n0 + 0) * ldb);
    const float4* b1 = (const float4*)(B + (size_t)(n0 + 1) * ldb);
    const float4* b2 = (const float4*)(B + (size_t)(n0 + 2) * ldb);
    const float4* b3 = (const float4*)(B + (size_t)(n0 + 3) * ldb);
    const int K4 = K >> 2;
    float acc[8][4] = {};
    for (int i = lane; i < K4; i += 32) {
        float4 v0 = b0[i], v1 = b1[i], v2 = b2[i], v3 = b3[i];
#pragma unroll
        for (int mi = 0; mi < 8; mi++) {
            float4 av = *(const float4*)(A + (size_t)(m0 + mi) * lda + i * 4);
            acc[mi][0] = fmaf(av.x, v0.x, fmaf(av.y, v0.y, fmaf(av.z, v0.z, fmaf(av.w, v0.w, acc[mi][0]))));
            acc[mi][1] = fmaf(av.x, v1.x, fmaf(av.y, v1.y, fmaf(av.z, v1.z, fmaf(av.w, v1.w, acc[mi][1]))));
            acc[mi][2] = fmaf(av.x, v2.x, fmaf(av.y, v2.y, fmaf(av.z, v2.z, fmaf(av.w, v2.w, acc[mi][2]))));
            acc[mi][3] = fmaf(av.x, v3.x, fmaf(av.y, v3.y, fmaf(av.z, v3.z, fmaf(av.w, v3.w, acc[mi][3]))));
        }
    }
#pragma unroll
    for (int mi = 0; mi < 8; mi++)
#pragma unroll
        for (int j = 0; j < 4; j++) {
            float a = acc[mi][j];
#pragma unroll
            for (int o = 16; o; o >>= 1) a += __shfl_xor_sync(0xffffffffu, a, o);
            acc[mi][j] = a;
        }
    if (lane == 0) {
#pragma unroll
        for (int mi = 0; mi < 8; mi++) {
            float* c = C + (size_t)(m0 + mi) * ldc + n0;
            if (bias) {
                c[0] = acc[mi][0] + bias[n0 + 0];
                c[1] = acc[mi][1] + bias[n0 + 1];
                c[2] = acc[mi][2] + bias[n0 + 2];
                c[3] = acc[mi][3] + bias[n0 + 3];
            } else {
                c[0] = acc[mi][0]; c[1] = acc[mi][1];
                c[2] = acc[mi][2]; c[3] = acc[mi][3];
            }
        }
    }
}

// ---------------- attention (3 phases for full BW) -------------------------
// Phase 1: scores[b,s] = dot(enc[b,s,:], v[b,:]) (+pad mask). grid (50, BB).
__global__ __launch_bounds__(256)
void attn_scores(const float* __restrict__ enc, const float* __restrict__ v,
                 const unsigned char* __restrict__ pad, float* __restrict__ sc)
{
    const int b = blockIdx.y;
    const int lane = threadIdx.x & 31, warp = threadIdx.x >> 5;
    const int s = blockIdx.x * 8 + warp;
    __shared__ __align__(16) float vsh[ENCD];
    ((float4*)vsh)[threadIdx.x] = ((const float4*)(v + (size_t)b * ENCD))[threadIdx.x];
    __syncthreads();
    const float4* row = (const float4*)(enc + ((size_t)b * SS + s) * ENCD);
    const float4* vv = (const float4*)vsh;
    float acc = 0.f;
#pragma unroll
    for (int i = 0; i < ENCD / 128; i++) {
        float4 e4 = row[lane + 32 * i];
        float4 v4 = vv[lane + 32 * i];
        acc = fmaf(e4.x, v4.x, acc);
        acc = fmaf(e4.y, v4.y, acc);
        acc = fmaf(e4.z, v4.z, acc);
        acc = fmaf(e4.w, v4.w, acc);
    }
#pragma unroll
    for (int o = 16; o; o >>= 1) acc += __shfl_xor_sync(0xffffffffu, acc, o);
    if (lane == 0)
        sc[(size_t)b * SS + s] = pad[(size_t)b * SS + s] ? -INFINITY : acc;
}

// Phase 2: softmax over S in place (+optional copy). grid BB, 128 thr.
__global__ __launch_bounds__(128)
void attn_softmax(float* __restrict__ sc, float* __restrict__ a_out)
{
    const int b = blockIdx.x, tid = threadIdx.x;
    const int lane = tid & 31, warp = tid >> 5;
    __shared__ float buf[SS];
    __shared__ float red[4];
    float* scb = sc + (size_t)b * SS;
    for (int i = tid; i < SS; i += 128) buf[i] = scb[i];
    __syncthreads();
    float m = -INFINITY;
    for (int i = tid; i < SS; i += 128) m = fmaxf(m, buf[i]);
#pragma unroll
    for (int o = 16; o; o >>= 1) m = fmaxf(m, __shfl_xor_sync(0xffffffffu, m, o));
    if (lane == 0) red[warp] = m;
    __syncthreads();
    m = fmaxf(fmaxf(red[0], red[1]), fmaxf(red[2], red[3]));
    float s = 0.f;
    for (int i = tid; i < SS; i += 128) {
        float e = __expf(buf[i] - m);
        buf[i] = e;
        s += e;
    }
#pragma unroll
    for (int o = 16; o; o >>= 1) s += __shfl_xor_sync(0xffffffffu, s, o);
    __syncthreads();
    if (lane == 0) red[warp] = s;
    __syncthreads();
    float inv = 1.f / (red[0] + red[1] + red[2] + red[3]);
    for (int i = tid; i < SS; i += 128) {
        float a = buf[i] * inv;
        scb[i] = a;
        if (a_out) a_out[(size_t)b * SS + i] = a;
    }
}

// Phase 3: weighted[b,e] = sum_s a[s] * enc[b,s,e]. grid (8, BB), 128 thr.
__global__ __launch_bounds__(128)
void attn_weighted(const float* __restrict__ enc, const float* __restrict__ sc,
                   float* __restrict__ wout, int wstride)
{
    const int b = blockIdx.y;
    const int e = blockIdx.x * 128 + threadIdx.x;
    __shared__ float a[SS];
    for (int i = threadIdx.x; i < SS; i += 128) a[i] = sc[(size_t)b * SS + i];
    __syncthreads();
    const float* p = enc + (size_t)b * SS * ENCD + e;
    float w0 = 0.f, w1 = 0.f, w2 = 0.f, w3 = 0.f;
    float w4 = 0.f, w5 = 0.f, w6 = 0.f, w7 = 0.f;
#pragma unroll 1
    for (int s = 0; s < SS; s += 8) {
        w0 = fmaf(a[s + 0], p[(size_t)(s + 0) * ENCD], w0);
        w1 = fmaf(a[s + 1], p[(size_t)(s + 1) * ENCD], w1);
        w2 = fmaf(a[s + 2], p[(size_t)(s + 2) * ENCD], w2);
        w3 = fmaf(a[s + 3], p[(size_t)(s + 3) * ENCD], w3);
        w4 = fmaf(a[s + 4], p[(size_t)(s + 4) * ENCD], w4);
        w5 = fmaf(a[s + 5], p[(size_t)(s + 5) * ENCD], w5);
        w6 = fmaf(a[s + 6], p[(size_t)(s + 6) * ENCD], w6);
        w7 = fmaf(a[s + 7], p[(size_t)(s + 7) * ENCD], w7);
    }
    wout[(size_t)b * wstride + e] = ((w0 + w1) + (w2 + w3)) + ((w4 + w5) + (w6 + w7));
}

// ---------------- small elementwise / glue kernels -------------------------
__global__ void embed_copy(const float* __restrict__ emb)
{
    int i = blockIdx.x * blockDim.x + threadIdx.x;
    if (i < BB * EMBD) {
        int b = i / EMBD, j = i - b * EMBD;
        g_rnn[(size_t)b * RNNK + j] = emb[i];
    }
}

__global__ void gru_combine(const float* __restrict__ h1,
                            float* __restrict__ out_h, int write_out)
{
    int i = blockIdx.x * blockDim.x + threadIdx.x;
    if (i >= BB * DECD) return;
    int b = i / DECD, j = i - b * DECD;
    const float* gx = g_gx + (size_t)b * G3;
    const float* gh = g_gh + (size_t)b * G3;
    float r = 1.f / (1.f + __expf(-(gx[j] + gh[j])));
    float z = 1.f / (1.f + __expf(-(gx[j + DECD] + gh[j + DECD])));
    float n = tanhf(gx[j + 2 * DECD] + r * gh[j + 2 * DECD]);
    float h = (1.f - z) * n + z * h1[i];
    g_hw[(size_t)b * HWK + j] = h;
    if (write_out) out_h[i] = h;
}

__global__ __launch_bounds__(128)
void pgen_kernel(const float* __restrict__ Wp, const float* __restrict__ bp)
{
    int b = blockIdx.x, tid = threadIdx.x;
    int lane = tid & 31, warp = tid >> 5;
    __shared__ float red[4];
    const float* hwb = g_hw + (size_t)b * HWK;
    float acc = 0.f;
    for (int i = tid; i < HWK; i += 128) acc = fmaf(hwb[i], Wp[i], acc);
#pragma unroll
    for (int o = 16; o; o >>= 1) acc += __shfl_xor_sync(0xffffffffu, acc, o);
    if (lane == 0) red[warp] = acc;
    __syncthreads();
    if (tid == 0) {
        float t = red[0] + red[1] + red[2] + red[3] + bp[0];
        g_pgen[b] = 1.f / (1.f + __expf(-t));
    }
}

// online max+sum softmax over VOCAB, then scaled write. grid BB, 1024 thr.
__global__ __launch_bounds__(1024)
void pvocab_kernel(float* __restrict__ pout)
{
    int b = blockIdx.x, tid = threadIdx.x;
    int lane = tid & 31, warp = tid >> 5;
    __shared__ float red_m[32], red_s[32];
    __shared__ float bc[2];
    const float* lg = g_logits + (size_t)b * VOCAB;

    float m = -INFINITY, s = 0.f;
    for (int i = tid; i < VOCAB; i += 1024) {
        float x = lg[i];
        float mo = m;
        m = fmaxf(m, x);
        s = s * __expf(mo - m) + __expf(x - m);
    }
#pragma unroll
    for (int o = 16; o; o >>= 1) {
        float m2 = __shfl_xor_sync(0xffffffffu, m, o);
        float s2 = __shfl_xor_sync(0xffffffffu, s, o);
        float M = fmaxf(m, m2);
        s = s * __expf(m - M) + s2 * __expf(m2 - M);
        m = M;
    }
    if (lane == 0) { red_m[warp] = m; red_s[warp] = s; }
    __syncthreads();
    if (tid == 0) {
        float M = red_m[0], S = red_s[0];
        for (int w = 1; w < 32; w++) {
            float M2 = fmaxf(M, red_m[w]);
            S = S * __expf(M - M2) + red_s[w] * __expf(red_m[w] - M2);
            M = M2;
        }
        bc[0] = M; bc[1] = S;
    }
    __syncthreads();
    m = bc[0];
    float scale = g_pgen[b] / bc[1];
    float* row = pout + (size_t)b * PVC;
    for (int i = tid; i < VOCAB; i += 1024) row[i] = __expf(lg[i] - m) * scale;
    for (int i = VOCAB + tid; i < PVC; i += 1024) row[i] = 0.f;
}

__global__ void scatter_kernel(const int* __restrict__ src, float* __restrict__ pout)
{
    int i = blockIdx.x * blockDim.x + threadIdx.x;
    if (i >= BB * SS) return;
    int b = i / SS;
    float val = (1.f - g_pgen[b]) * g_a2[i];
    atomicAdd(pout + (size_t)b * PVC + src[i], val);
}

// ---------------- launch ---------------------------------------------------
extern "C" void kernel_launch(void* const* d_in, const int* in_sizes, int n_in,
                              void* d_out, int out_size)
{
    int off = (n_in >= 16) ? 0 : -1;
    const float* embedded = (const float*)d_in[0];
    const float* enc      = (const float*)d_in[1];
    const float* h1       = (const float*)d_in[2];
    const unsigned char* pad = (const unsigned char*)d_in[3];
    const int*   src      = (const int*)d_in[5 + off];
    const float* W_attn1  = (const float*)d_in[6 + off];
    const float* W_attn2  = (const float*)d_in[7 + off];
    const float* W_ih     = (const float*)d_in[8 + off];
    const float* W_hh     = (const float*)d_in[9 + off];
    const float* b_ih     = (const float*)d_in[10 + off];
    const float* b_hh     = (const float*)d_in[11 + off];
    const float* W_out    = (const float*)d_in[12 + off];
    const float* b_out    = (const float*)d_in[13 + off];
    const float* W_p      = (const float*)d_in[14 + off];
    const float* b_p      = (const float*)d_in[15 + off];
    float* pout = (float*)d_out;

    float *v, *rnn, *gx, *gh, *hw, *logits, *sc, *a2;
    cudaGetSymbolAddress((void**)&v, g_v);
    cudaGetSymbolAddress((void**)&rnn, g_rnn);
    cudaGetSymbolAddress((void**)&gx, g_gx);
    cudaGetSymbolAddress((void**)&gh, g_gh);
    cudaGetSymbolAddress((void**)&hw, g_hw);
    cudaGetSymbolAddress((void**)&logits, g_logits);
    cudaGetSymbolAddress((void**)&sc, g_sc);
    cudaGetSymbolAddress((void**)&a2, g_a2);

    cudaFuncSetAttribute(gemm_mma, cudaFuncAttributeMaxDynamicSharedMemorySize, MM_SMEM);

    // 1. rnn[:, 0:EMB] = embedded
    embed_copy<<<(BB * EMBD + 255) / 256, 256>>>(embedded);
    // 2. gh = h1 @ W_hh^T + b_hh
    gemm_warp8m<<<dim3((G3 + 31) / 32, BB / 8), 256>>>(h1, DECD, W_hh, DECD,
                                                       gh, G3, b_hh, G3, DECD);
    // 3. v1 = h1 @ W_attn1^T
    gemm_warp8m<<<dim3(ENCD / 32, BB / 8), 256>>>(h1, DECD, W_attn1, DECD,
                                                  v, ENCD, nullptr, ENCD, DECD);
    // 4. attention 1 -> weighted1 into rnn[:, EMB:]
    attn_scores<<<dim3(SS / 8, BB), 256>>>(enc, v, pad, sc);
    attn_softmax<<<BB, 128>>>(sc, nullptr);
    attn_weighted<<<dim3(ENCD / 128, BB), 128>>>(enc, sc, rnn + EMBD, RNNK);
    // 5. gx = rnn @ W_ih^T + b_ih
    gemm_warp8m<<<dim3((G3 + 31) / 32, BB / 8), 256>>>(rnn, RNNK, W_ih, RNNK,
                                                       gx, G3, b_ih, G3, RNNK);
    // 6. GRU combine -> hw[:, 0:DEC] (= h_new)
    int wtail = (out_size >= BB * PVC + BB * DECD) ? 1 : 0;
    gru_combine<<<(BB * DECD + 255) / 256, 256>>>(h1, pout + (size_t)BB * PVC, wtail);
    // 7. v2 = h_new @ W_attn2^T
    gemm_warp8m<<<dim3(ENCD / 32, BB / 8), 256>>>(hw, HWK, W_attn2, DECD,
                                                  v, ENCD, nullptr, ENCD, DECD);
    // 8. attention 2 -> weighted2 into hw[:, DEC:], save a2
    attn_scores<<<dim3(SS / 8, BB), 256>>>(enc, v, pad, sc);
    attn_softmax<<<BB, 128>>>(sc, a2);
    attn_weighted<<<dim3(ENCD / 128, BB), 128>>>(enc, sc, hw + DECD, HWK);
    // 9. p_gen
    pgen_kernel<<<BB, 128>>>(W_p, b_p);
    // 10. convert A once, then logits = hw @ W_out^T + b_out
    convA_kernel<<<BB, 256>>>();
    gemm_mma<<<dim3((VOCAB + 127) / 128), 256, MM_SMEM>>>(W_out, HWK, logits,
                                                          VOCAB, b_out, VOCAB, HWK);
    // 11. p_out[:, :VOCAB] = p_gen * softmax(logits); ext cols zeroed
    pvocab_kernel<<<BB, 1024>>>(pout);
    // 12. scatter-add (1-p_gen)*a2 at source ids
    scatter_kernel<<<(BB * SS + 255) / 256, 256>>>(src, pout);
}

// round 7
// speedup vs baseline: 3.2982x; 1.3840x over previous
#include <cuda_runtime.h>
#include <cuda_fp16.h>
#include <math.h>
#include <stdint.h>

#define BB 128
#define SS 400
#define ENCD 1024
#define DECD 300
#define EMBD 128
#define VOCAB 50000
#define MAXOOV 50
#define PVC (VOCAB + MAXOOV)   /* 50050 */
#define RNNK (EMBD + ENCD)     /* 1152 */
#define HWK (DECD + ENCD)      /* 1324 */
#define G3 (3 * DECD)          /* 900 */
#define KPAD 1344              /* HWK padded to multiple of 32 */

// ---------------- scratch (static device globals; no allocation) ----------
__device__ __align__(256) float g_v[BB * ENCD];
__device__ __align__(256) float g_rnn[BB * RNNK];
__device__ __align__(256) float g_gx[BB * G3];
__device__ __align__(256) float g_gh[BB * G3];
__device__ __align__(256) float g_hw[BB * HWK];
__device__ __align__(256) float g_sc[BB * SS];
__device__ __align__(256) float g_a2[BB * SS];
__device__ __align__(256) float g_pgen[BB];
__device__ __align__(256) float g_logits[(size_t)BB * VOCAB];
__device__ __align__(256) __half g_Af[BB * KPAD];

// ======================= helpers ==========================================
__device__ __forceinline__ uint32_t smem_u32(const void* p) {
    uint32_t a;
    asm("{ .reg .u64 t; cvta.to.shared.u64 t, %1; cvt.u32.u64 %0, t; }"
        : "=r"(a) : "l"(p));
    return a;
}

__device__ __forceinline__ void ldmx4(uint32_t* r, uint32_t addr) {
    asm volatile("ldmatrix.sync.aligned.m8n8.x4.shared.b16 {%0,%1,%2,%3}, [%4];"
                 : "=r"(r[0]), "=r"(r[1]), "=r"(r[2]), "=r"(r[3]) : "r"(addr));
}

__device__ __forceinline__ void mma16816h(float* d, const uint32_t* a,
                                          uint32_t b0, uint32_t b1) {
    asm volatile(
        "mma.sync.aligned.m16n8k16.row.col.f32.f16.f16.f32 "
        "{%0,%1,%2,%3}, {%4,%5,%6,%7}, {%8,%9}, {%0,%1,%2,%3};"
        : "+f"(d[0]), "+f"(d[1]), "+f"(d[2]), "+f"(d[3])
        : "r"(a[0]), "r"(a[1]), "r"(a[2]), "r"(a[3]), "r"(b0), "r"(b1));
}

__device__ __forceinline__ void cp16(uint32_t dst, const void* src) {
    asm volatile("cp.async.cg.shared.global [%0], [%1], 16;"
                 :: "r"(dst), "l"(src) : "memory");
}
__device__ __forceinline__ void cp_commit() {
    asm volatile("cp.async.commit_group;" ::: "memory");
}
__device__ __forceinline__ void cp_wait0() {
    asm volatile("cp.async.wait_group 0;" ::: "memory");
}

// fp32x4 -> fp16x4 packed store (8 bytes)
__device__ __forceinline__ void cvt_store_h4(__half* dst, float4 v) {
    __half2 a = __floats2half2_rn(v.x, v.y);
    __half2 b = __floats2half2_rn(v.z, v.w);
    uint32_t ua, ub;
    ua = *(uint32_t*)&a;
    ub = *(uint32_t*)&b;
    *(uint2*)dst = make_uint2(ua, ub);
}

// convert A (g_hw fp32) -> g_Af fp16, zero-padded to KPAD
__global__ void convA_kernel()
{
    int b = blockIdx.x;
    for (int k = threadIdx.x; k < KPAD; k += blockDim.x) {
        float x = (k < HWK) ? g_hw[(size_t)b * HWK + k] : 0.f;
        g_Af[(size_t)b * KPAD + k] = __float2half_rn(x);
    }
}

// ====================================================================
// Tensor-core logits GEMM via mma.sync: C[128,N] = A[128,K]*B[N,K]^T + bias.
// Single fp16 operands (err ~3e-4 logit-abs, well inside 1e-3 budget).
// A pre-converted fp16 in global (cp.async). B LDG-staged in regs BEFORE
// compute, converted+STS AFTER compute — DRAM latency hides behind MMAs.
// 128x128 CTA tile, K chunks of 32, double-buffered, 8 warps x (64x32).
// ====================================================================
#define CH 32
#define NCH (KPAD / CH)             /* 42 */
#define ASTRIDE 40                  /* halves per smem row */
#define ARR_B (128 * ASTRIDE * 2)   /* 10240 bytes per array */
#define BUF_B (2 * ARR_B)           /* Af, Bf = 20480 */
#define MM_SMEM (2 * BUF_B)         /* 40960 */

__global__ __launch_bounds__(256, 2)
void gemm_mma(const float* __restrict__ B, int ldb,
              float* __restrict__ C, int ldc,
              const float* __restrict__ bias, int N, int K)
{
    extern __shared__ char smem[];
    const uint32_t sbase = smem_u32(smem);
    const int tid = threadIdx.x;
    const int wid = tid >> 5, lid = tid & 31;
    const int warp_m = (wid >> 2) * 64;   // 0, 64
    const int warp_n = (wid & 3) * 32;    // 0..96
    const int bn = blockIdx.x * 128;

    float acc[4][4][4] = {};
    float4 stB[4];

    // cp.async A tile: 128 rows x 32 halves (64 B/row); 2 x 16B per thread
    const int a_half = tid >> 7;          // 0 or 1 (which 16 halves)
    const int a_row = tid & 127;
    auto cpA = [&](int c, int buf) {
        uint32_t dst = sbase + buf * BUF_B + a_row * (ASTRIDE * 2) + a_half * 32;
        const char* src = (const char*)(g_Af + (size_t)a_row * KPAD + c * CH) + a_half * 32;
        cp16(dst, src);
        cp16(dst + 16, src + 16);
    };

    auto ldgB = [&](int c) {
        const int kb = c * CH;
#pragma unroll
        for (int t = 0; t < 4; t++) {
            int idx = tid + t * 256;
            int row = idx >> 3;
            int c4 = (idx & 7) << 2;
            int gk = kb + c4;
            float4 v = make_float4(0.f, 0.f, 0.f, 0.f);
            if (gk < K) {                 // K % 4 == 0
                int n = bn + row;
                if (n < N) v = *(const float4*)(B + (size_t)n * ldb + gk);
            }
            stB[t] = v;
        }
    };
    auto stsB = [&](int buf) {
        __half* Bf = (__half*)(smem + buf * BUF_B + ARR_B);
#pragma unroll
        for (int t = 0; t < 4; t++) {
            int idx = tid + t * 256;
            int row = idx >> 3;
            int c4 = (idx & 7) << 2;
            cvt_store_h4(Bf + row * ASTRIDE + c4, stB[t]);
        }
    };

    auto compute_chunk = [&](int buf) {
        const uint32_t Af = sbase + buf * BUF_B;
        const uint32_t Bf = Af + ARR_B;
        const int lrow = lid & 15;
        const int lcol = (lid >> 4) << 3;
#pragma unroll
        for (int kk = 0; kk < CH; kk += 16) {
            uint32_t b0[4], b1[4];
            {
                uint32_t o0 = (uint32_t)(((warp_n + 0  + lrow) * ASTRIDE + kk + lcol) * 2);
                uint32_t o1 = (uint32_t)(((warp_n + 16 + lrow) * ASTRIDE + kk + lcol) * 2);
                ldmx4(b0, Bf + o0);
                ldmx4(b1, Bf + o1);
            }
#pragma unroll
            for (int fm = 0; fm < 4; fm++) {
                uint32_t ah[4];
                uint32_t ao = (uint32_t)(((warp_m + fm * 16 + lrow) * ASTRIDE + kk + lcol) * 2);
                ldmx4(ah, Af + ao);
                mma16816h(acc[fm][0], ah, b0[0], b0[2]);
                mma16816h(acc[fm][1], ah, b0[1], b0[3]);
                mma16816h(acc[fm][2], ah, b1[0], b1[2]);
                mma16816h(acc[fm][3], ah, b1[1], b1[3]);
            }
        }
    };

    // prologue
    cpA(0, 0); cp_commit();
    ldgB(0);
    stsB(0);
    cp_wait0();
    __syncthreads();

    for (int c = 0; c < NCH; c++) {
        const int buf = c & 1, nb = buf ^ 1;
        if (c + 1 < NCH) {
            cpA(c + 1, nb); cp_commit();
            ldgB(c + 1);              // LDG issued; latency hidden by MMAs
        }
        compute_chunk(buf);
        if (c + 1 < NCH) {
            stsB(nb);
            cp_wait0();
        }
        __syncthreads();
    }

    // epilogue
    const int erow = lid >> 2;
    const int ecol = (lid & 3) << 1;
#pragma unroll
    for (int fm = 0; fm < 4; fm++) {
#pragma unroll
        for (int fn = 0; fn < 4; fn++) {
            int row = warp_m + fm * 16 + erow;
            int col = bn + warp_n + fn * 8 + ecol;
            if (col < N) {
                float b0 = bias[col], b1 = bias[col + 1];
                float* d = acc[fm][fn];
                *(float2*)(C + (size_t)row * ldc + col) =
                    make_float2(d[0] + b0, d[1] + b1);
                *(float2*)(C + (size_t)(row + 8) * ldc + col) =
                    make_float2(d[2] + b0, d[3] + b1);
            }
        }
    }
}

// ====================================================================
// Small-GEMM: C[M,N] = A[M,K]*B[N,K]^T (+bias). Warp computes 8 m-rows
// x 4 n-cols (B loads reused 8x). grid = (ceil(N/32), M/8), 256 thr.
// ====================================================================
__global__ __launch_bounds__(256)
void gemm_warp8m(const float* __restrict__ A, int lda,
                 const float* __restrict__ B, int ldb,
                 float* __restrict__ C, int ldc,
                 const float* __restrict__ bias, int N, int K)
{
    const int m0 = blockIdx.y * 8;
    const int warp = threadIdx.x >> 5, lane = threadIdx.x & 31;
    const int n0 = blockIdx.x * 32 + warp * 4;
    if (n0 >= N) return;
    const float4* b0 = (const float4*)(B + (size_t)(n0 + 0) * ldb);
    const float4* b1 = (const float4*)(B + (size_t)(n0 + 1) * ldb);
    const float4* b2 = (const float4*)(B + (size_t)(n0 + 2) * ldb);
    const float4* b3 = (const float4*)(B + (size_t)(n0 + 3) * ldb);
    const int K4 = K >> 2;
    float acc[8][4] = {};
    for (int i = lane; i < K4; i += 32) {
        float4 v0 = b0[i], v1 = b1[i], v2 = b2[i], v3 = b3[i];
#pragma unroll
        for (int mi = 0; mi < 8; mi++) {
            float4 av = *(const float4*)(A + (size_t)(m0 + mi) * lda + i * 4);
            acc[mi][0] = fmaf(av.x, v0.x, fmaf(av.y, v0.y, fmaf(av.z, v0.z, fmaf(av.w, v0.w, acc[mi][0]))));
            acc[mi][1] = fmaf(av.x, v1.x, fmaf(av.y, v1.y, fmaf(av.z, v1.z, fmaf(av.w, v1.w, acc[mi][1]))));
            acc[mi][2] = fmaf(av.x, v2.x, fmaf(av.y, v2.y, fmaf(av.z, v2.z, fmaf(av.w, v2.w, acc[mi][2]))));
            acc[mi][3] = fmaf(av.x, v3.x, fmaf(av.y, v3.y, fmaf(av.z, v3.z, fmaf(av.w, v3.w, acc[mi][3]))));
        }
    }
#pragma unroll
    for (int mi = 0; mi < 8; mi++)
#pragma unroll
        for (int j = 0; j < 4; j++) {
            float a = acc[mi][j];
#pragma unroll
            for (int o = 16; o; o >>= 1) a += __shfl_xor_sync(0xffffffffu, a, o);
            acc[mi][j] = a;
        }
    if (lane == 0) {
#pragma unroll
        for (int mi = 0; mi < 8; mi++) {
            float* c = C + (size_t)(m0 + mi) * ldc + n0;
            if (bias) {
                c[0] = acc[mi][0] + bias[n0 + 0];
                c[1] = acc[mi][1] + bias[n0 + 1];
                c[2] = acc[mi][2] + bias[n0 + 2];
                c[3] = acc[mi][3] + bias[n0 + 3];
            } else {
                c[0] = acc[mi][0]; c[1] = acc[mi][1];
                c[2] = acc[mi][2]; c[3] = acc[mi][3];
            }
        }
    }
}

// ---------------- attention (3 phases for full BW) -------------------------
// Phase 1: scores[b,s] = dot(enc[b,s,:], v[b,:]) (+pad mask). grid (50, BB).
__global__ __launch_bounds__(256)
void attn_scores(const float* __restrict__ enc, const float* __restrict__ v,
                 const unsigned char* __restrict__ pad, float* __restrict__ sc)
{
    const int b = blockIdx.y;
    const int lane = threadIdx.x & 31, warp = threadIdx.x >> 5;
    const int s = blockIdx.x * 8 + warp;
    __shared__ __align__(16) float vsh[ENCD];
    ((float4*)vsh)[threadIdx.x] = ((const float4*)(v + (size_t)b * ENCD))[threadIdx.x];
    __syncthreads();
    const float4* row = (const float4*)(enc + ((size_t)b * SS + s) * ENCD);
    const float4* vv = (const float4*)vsh;
    float acc = 0.f;
#pragma unroll
    for (int i = 0; i < ENCD / 128; i++) {
        float4 e4 = row[lane + 32 * i];
        float4 v4 = vv[lane + 32 * i];
        acc = fmaf(e4.x, v4.x, acc);
        acc = fmaf(e4.y, v4.y, acc);
        acc = fmaf(e4.z, v4.z, acc);
        acc = fmaf(e4.w, v4.w, acc);
    }
#pragma unroll
    for (int o = 16; o; o >>= 1) acc += __shfl_xor_sync(0xffffffffu, acc, o);
    if (lane == 0)
        sc[(size_t)b * SS + s] = pad[(size_t)b * SS + s] ? -INFINITY : acc;
}

// Phase 2: softmax over S in place (+optional copy). grid BB, 128 thr.
__global__ __launch_bounds__(128)
void attn_softmax(float* __restrict__ sc, float* __restrict__ a_out)
{
    const int b = blockIdx.x, tid = threadIdx.x;
    const int lane = tid & 31, warp = tid >> 5;
    __shared__ float buf[SS];
    __shared__ float red[4];
    float* scb = sc + (size_t)b * SS;
    for (int i = tid; i < SS; i += 128) buf[i] = scb[i];
    __syncthreads();
    float m = -INFINITY;
    for (int i = tid; i < SS; i += 128) m = fmaxf(m, buf[i]);
#pragma unroll
    for (int o = 16; o; o >>= 1) m = fmaxf(m, __shfl_xor_sync(0xffffffffu, m, o));
    if (lane == 0) red[warp] = m;
    __syncthreads();
    m = fmaxf(fmaxf(red[0], red[1]), fmaxf(red[2], red[3]));
    float s = 0.f;
    for (int i = tid; i < SS; i += 128) {
        float e = __expf(buf[i] - m);
        buf[i] = e;
        s += e;
    }
#pragma unroll
    for (int o = 16; o; o >>= 1) s += __shfl_xor_sync(0xffffffffu, s, o);
    __syncthreads();
    if (lane == 0) red[warp] = s;
    __syncthreads();
    float inv = 1.f / (red[0] + red[1] + red[2] + red[3]);
    for (int i = tid; i < SS; i += 128) {
        float a = buf[i] * inv;
        scb[i] = a;
        if (a_out) a_out[(size_t)b * SS + i] = a;
    }
}

// Phase 3: weighted[b,e] = sum_s a[s] * enc[b,s,e]. grid (8, BB), 128 thr.
__global__ __launch_bounds__(128)
void attn_weighted(const float* __restrict__ enc, const float* __restrict__ sc,
                   float* __restrict__ wout, int wstride)
{
    const int b = blockIdx.y;
    const int e = blockIdx.x * 128 + threadIdx.x;
    __shared__ float a[SS];
    for (int i = threadIdx.x; i < SS; i += 128) a[i] = sc[(size_t)b * SS + i];
    __syncthreads();
    const float* p = enc + (size_t)b * SS * ENCD + e;
    float w0 = 0.f, w1 = 0.f, w2 = 0.f, w3 = 0.f;
    float w4 = 0.f, w5 = 0.f, w6 = 0.f, w7 = 0.f;
#pragma unroll 1
    for (int s = 0; s < SS; s += 8) {
        w0 = fmaf(a[s + 0], p[(size_t)(s + 0) * ENCD], w0);
        w1 = fmaf(a[s + 1], p[(size_t)(s + 1) * ENCD], w1);
        w2 = fmaf(a[s + 2], p[(size_t)(s + 2) * ENCD], w2);
        w3 = fmaf(a[s + 3], p[(size_t)(s + 3) * ENCD], w3);
        w4 = fmaf(a[s + 4], p[(size_t)(s + 4) * ENCD], w4);
        w5 = fmaf(a[s + 5], p[(size_t)(s + 5) * ENCD], w5);
        w6 = fmaf(a[s + 6], p[(size_t)(s + 6) * ENCD], w6);
        w7 = fmaf(a[s + 7], p[(size_t)(s + 7) * ENCD], w7);
    }
    wout[(size_t)b * wstride + e] = ((w0 + w1) + (w2 + w3)) + ((w4 + w5) + (w6 + w7));
}

// ---------------- small elementwise / glue kernels -------------------------
__global__ void embed_copy(const float* __restrict__ emb)
{
    int i = blockIdx.x * blockDim.x + threadIdx.x;
    if (i < BB * EMBD) {
        int b = i / EMBD, j = i - b * EMBD;
        g_rnn[(size_t)b * RNNK + j] = emb[i];
    }
}

__global__ void gru_combine(const float* __restrict__ h1,
                            float* __restrict__ out_h, int write_out)
{
    int i = blockIdx.x * blockDim.x + threadIdx.x;
    if (i >= BB * DECD) return;
    int b = i / DECD, j = i - b * DECD;
    const float* gx = g_gx + (size_t)b * G3;
    const float* gh = g_gh + (size_t)b * G3;
    float r = 1.f / (1.f + __expf(-(gx[j] + gh[j])));
    float z = 1.f / (1.f + __expf(-(gx[j + DECD] + gh[j + DECD])));
    float n = tanhf(gx[j + 2 * DECD] + r * gh[j + 2 * DECD]);
    float h = (1.f - z) * n + z * h1[i];
    g_hw[(size_t)b * HWK + j] = h;
    if (write_out) out_h[i] = h;
}

__global__ __launch_bounds__(128)
void pgen_kernel(const float* __restrict__ Wp, const float* __restrict__ bp)
{
    int b = blockIdx.x, tid = threadIdx.x;
    int lane = tid & 31, warp = tid >> 5;
    __shared__ float red[4];
    const float* hwb = g_hw + (size_t)b * HWK;
    float acc = 0.f;
    for (int i = tid; i < HWK; i += 128) acc = fmaf(hwb[i], Wp[i], acc);
#pragma unroll
    for (int o = 16; o; o >>= 1) acc += __shfl_xor_sync(0xffffffffu, acc, o);
    if (lane == 0) red[warp] = acc;
    __syncthreads();
    if (tid == 0) {
        float t = red[0] + red[1] + red[2] + red[3] + bp[0];
        g_pgen[b] = 1.f / (1.f + __expf(-t));
    }
}

// online max+sum softmax over VOCAB, then scaled write. grid BB, 1024 thr.
__global__ __launch_bounds__(1024)
void pvocab_kernel(float* __restrict__ pout)
{
    int b = blockIdx.x, tid = threadIdx.x;
    int lane = tid & 31, warp = tid >> 5;
    __shared__ float red_m[32], red_s[32];
    __shared__ float bc[2];
    const float* lg = g_logits + (size_t)b * VOCAB;

    float m = -INFINITY, s = 0.f;
    for (int i = tid; i < VOCAB; i += 1024) {
        float x = lg[i];
        float mo = m;
        m = fmaxf(m, x);
        s = s * __expf(mo - m) + __expf(x - m);
    }
#pragma unroll
    for (int o = 16; o; o >>= 1) {
        float m2 = __shfl_xor_sync(0xffffffffu, m, o);
        float s2 = __shfl_xor_sync(0xffffffffu, s, o);
        float M = fmaxf(m, m2);
        s = s * __expf(m - M) + s2 * __expf(m2 - M);
        m = M;
    }
    if (lane == 0) { red_m[warp] = m; red_s[warp] = s; }
    __syncthreads();
    if (tid == 0) {
        float M = red_m[0], S = red_s[0];
        for (int w = 1; w < 32; w++) {
            float M2 = fmaxf(M, red_m[w]);
            S = S * __expf(M - M2) + red_s[w] * __expf(red_m[w] - M2);
            M = M2;
        }
        bc[0] = M; bc[1] = S;
    }
    __syncthreads();
    m = bc[0];
    float scale = g_pgen[b] / bc[1];
    float* row = pout + (size_t)b * PVC;
    for (int i = tid; i < VOCAB; i += 1024) row[i] = __expf(lg[i] - m) * scale;
    for (int i = VOCAB + tid; i < PVC; i += 1024) row[i] = 0.f;
}

__global__ void scatter_kernel(const int* __restrict__ src, float* __restrict__ pout)
{
    int i = blockIdx.x * blockDim.x + threadIdx.x;
    if (i >= BB * SS) return;
    int b = i / SS;
    float val = (1.f - g_pgen[b]) * g_a2[i];
    atomicAdd(pout + (size_t)b * PVC + src[i], val);
}

// ---------------- launch ---------------------------------------------------
extern "C" void kernel_launch(void* const* d_in, const int* in_sizes, int n_in,
                              void* d_out, int out_size)
{
    int off = (n_in >= 16) ? 0 : -1;
    const float* embedded = (const float*)d_in[0];
    const float* enc      = (const float*)d_in[1];
    const float* h1       = (const float*)d_in[2];
    const unsigned char* pad = (const unsigned char*)d_in[3];
    const int*   src      = (const int*)d_in[5 + off];
    const float* W_attn1  = (const float*)d_in[6 + off];
    const float* W_attn2  = (const float*)d_in[7 + off];
    const float* W_ih     = (const float*)d_in[8 + off];
    const float* W_hh     = (const float*)d_in[9 + off];
    const float* b_ih     = (const float*)d_in[10 + off];
    const float* b_hh     = (const float*)d_in[11 + off];
    const float* W_out    = (const float*)d_in[12 + off];
    const float* b_out    = (const float*)d_in[13 + off];
    const float* W_p      = (const float*)d_in[14 + off];
    const float* b_p      = (const float*)d_in[15 + off];
    float* pout = (float*)d_out;

    float *v, *rnn, *gx, *gh, *hw, *logits, *sc, *a2;
    cudaGetSymbolAddress((void**)&v, g_v);
    cudaGetSymbolAddress((void**)&rnn, g_rnn);
    cudaGetSymbolAddress((void**)&gx, g_gx);
    cudaGetSymbolAddress((void**)&gh, g_gh);
    cudaGetSymbolAddress((void**)&hw, g_hw);
    cudaGetSymbolAddress((void**)&logits, g_logits);
    cudaGetSymbolAddress((void**)&sc, g_sc);
    cudaGetSymbolAddress((void**)&a2, g_a2);

    cudaFuncSetAttribute(gemm_mma, cudaFuncAttributeMaxDynamicSharedMemorySize, MM_SMEM);

    // 1. rnn[:, 0:EMB] = embedded
    embed_copy<<<(BB * EMBD + 255) / 256, 256>>>(embedded);
    // 2. gh = h1 @ W_hh^T + b_hh
    gemm_warp8m<<<dim3((G3 + 31) / 32, BB / 8), 256>>>(h1, DECD, W_hh, DECD,
                                                       gh, G3, b_hh, G3, DECD);
    // 3. v1 = h1 @ W_attn1^T
    gemm_warp8m<<<dim3(ENCD / 32, BB / 8), 256>>>(h1, DECD, W_attn1, DECD,
                                                  v, ENCD, nullptr, ENCD, DECD);
    // 4. attention 1 -> weighted1 into rnn[:, EMB:]
    attn_scores<<<dim3(SS / 8, BB), 256>>>(enc, v, pad, sc);
    attn_softmax<<<BB, 128>>>(sc, nullptr);
    attn_weighted<<<dim3(ENCD / 128, BB), 128>>>(enc, sc, rnn + EMBD, RNNK);
    // 5. gx = rnn @ W_ih^T + b_ih
    gemm_warp8m<<<dim3((G3 + 31) / 32, BB / 8), 256>>>(rnn, RNNK, W_ih, RNNK,
                                                       gx, G3, b_ih, G3, RNNK);
    // 6. GRU combine -> hw[:, 0:DEC] (= h_new)
    int wtail = (out_size >= BB * PVC + BB * DECD) ? 1 : 0;
    gru_combine<<<(BB * DECD + 255) / 256, 256>>>(h1, pout + (size_t)BB * PVC, wtail);
    // 7. v2 = h_new @ W_attn2^T
    gemm_warp8m<<<dim3(ENCD / 32, BB / 8), 256>>>(hw, HWK, W_attn2, DECD,
                                                  v, ENCD, nullptr, ENCD, DECD);
    // 8. attention 2 -> weighted2 into hw[:, DEC:], save a2
    attn_scores<<<dim3(SS / 8, BB), 256>>>(enc, v, pad, sc);
    attn_softmax<<<BB, 128>>>(sc, a2);
    attn_weighted<<<dim3(ENCD / 128, BB), 128>>>(enc, sc, hw + DECD, HWK);
    // 9. p_gen
    pgen_kernel<<<BB, 128>>>(W_p, b_p);
    // 10. convert A once (fp16), then logits = hw @ W_out^T + b_out
    convA_kernel<<<BB, 256>>>();
    gemm_mma<<<dim3((VOCAB + 127) / 128), 256, MM_SMEM>>>(W_out, HWK, logits,
                                                          VOCAB, b_out, VOCAB, HWK);
    // 11. p_out[:, :VOCAB] = p_gen * softmax(logits); ext cols zeroed
    pvocab_kernel<<<BB, 1024>>>(pout);
    // 12. scatter-add (1-p_gen)*a2 at source ids
    scatter_kernel<<<(BB * SS + 255) / 256, 256>>>(src, pout);
}